// round 4
// baseline (speedup 1.0000x reference)
#include <cuda_runtime.h>
#include <cstdint>
#include <cstddef>

#define Bx 32
#define Tt 64
#define Dd 1024
#define Hh 1024
#define Vv 32000
#define MX 100
#define BH (Bx*Hh)

typedef unsigned long long ull;

// ---------------- device scratch (no allocations allowed) ----------------
__device__ float g_hs[(size_t)Tt*BH];   // teacher-forced hidden states [T][B][H]
__device__ float g_zeros[BH];
__device__ float g_ctf[BH];
__device__ float g_cgr[BH];
__device__ float g_hg0[BH];
__device__ float g_hg1[BH];
__device__ ull g_slots[64];  // two ping-pong buffers of 32

// ---------------- packed fp32x2 helpers (Blackwell FFMA2) ----------------
__device__ __forceinline__ ull fma2(ull a, ull b, ull c) {
    ull d;
    asm("fma.rn.f32x2 %0, %1, %2, %3;" : "=l"(d) : "l"(a), "l"(b), "l"(c));
    return d;
}
__device__ __forceinline__ ull add2(ull a, ull b) {
    ull d;
    asm("add.rn.f32x2 %0, %1, %2;" : "=l"(d) : "l"(a), "l"(b));
    return d;
}
__device__ __forceinline__ ull dup2(float w) {
    ull d; asm("mov.b64 %0, {%1, %1};" : "=l"(d) : "f"(w)); return d;
}
__device__ __forceinline__ ull pack2(float lo, float hi) {
    ull d; asm("mov.b64 %0, {%1, %2};" : "=l"(d) : "f"(lo), "f"(hi)); return d;
}
__device__ __forceinline__ float lo2(ull v) { return __uint_as_float((unsigned int)(v & 0xFFFFFFFFull)); }
__device__ __forceinline__ float hi2(ull v) { return __uint_as_float((unsigned int)(v >> 32)); }

// ordered-float key: monotonic uint mapping of float
__device__ __forceinline__ unsigned int fkey(float f) {
    unsigned int u = __float_as_uint(f);
    return (u & 0x80000000u) ? ~u : (u | 0x80000000u);
}

__global__ void init_kernel() {
    int i = blockIdx.x * blockDim.x + threadIdx.x;
    if (i < BH) { g_zeros[i] = 0.f; g_ctf[i] = 0.f; g_cgr[i] = 0.f; }
}

// ---------------- fused LSTM cell step v3 ----------------
// 128 blocks x 256 threads. Block: 32 (gate,j) cols x 32 batches, K=2048.
// 16-way interleaved split-K (slice = k mod 16). Thread tile: 8 cols x 8 batches.
// Warp = 2 adjacent slices x 4 col-groups(=gates) x 4 batch-groups.
// w_sh transposed [col][k] pitch 65; x_sh [k][b] pitch 34 (LDS.64 batch pairs).
#define WLP 65
#define XLP 34
#define SB_W  16640            // [2][32][65] floats
#define SB_X  17408            // [2][64][34] floats
__global__ void __launch_bounds__(256) lstm_cell(
    const float* __restrict__ Wx, const float* __restrict__ Wh,
    const float* __restrict__ bias, const float* __restrict__ Wo,
    const int* __restrict__ tok_src, int tok_stride, int mode,
    const ull* __restrict__ slots_in,
    ull* __restrict__ slots_reset,
    float* __restrict__ best_prev_out,
    const float* __restrict__ h_in, float* __restrict__ h_out,
    float* __restrict__ c)
{
    __shared__ __align__(16) char sbuf[SB_W + SB_X];   // union: staging | red
    float (*w_sh)[32][WLP] = (float (*)[32][WLP])sbuf;
    float (*x_sh)[64][XLP] = (float (*)[64][XLP])(sbuf + SB_W);
    ull   (*red)[16][32]   = (ull (*)[16][32])sbuf;    // [8][16][32] = 32KB
    __shared__ float gate_sh[32][33];
    __shared__ int tok_sh[32];

    const int tid = threadIdx.x;
    const int jbase = blockIdx.x * 8;

    if (tid < 32) {
        int tk;
        if (mode == 0) tk = tok_src[tid * tok_stride];
        else if (mode == 1) tk = 1;  // GO token
        else {
            ull p = slots_in[tid];
            tk = (int)(0xFFFFFFFFu - (unsigned int)(p & 0xFFFFFFFFull));
            if (blockIdx.x == 0 && best_prev_out) best_prev_out[tid] = (float)tk;
        }
        tok_sh[tid] = tk;
        if (blockIdx.x == 0 && slots_reset) slots_reset[tid] = 0ull;
    }
    __syncthreads();

    // loader indices
    const int wkr = tid >> 2;          // 0..63 : w row within chunk
    const int wg  = tid & 3;           // gate for w loader
    const int xb  = tid >> 3;          // 0..31 : batch for x loader
    const int xkq = tid & 7;           // k-octet for x loader
    const int mytok = tok_sh[xb];

    // compute indices
    const int lane = tid & 31, warp = tid >> 5;
    const int slice = 2 * warp + (lane & 1);   // 0..15
    const int bg = (lane >> 1) & 3;            // batch group
    const int cg = lane >> 3;                  // col group == gate

    ull acc[8][4];
    #pragma unroll
    for (int i = 0; i < 8; i++)
        #pragma unroll
        for (int j = 0; j < 4; j++) acc[i][j] = 0ull;

    float4 wv0, wv1, xv0, xv1;

    // prologue: load chunk 0 (k0 = 0 -> Wx / Wo)
    {
        const float* wp = Wx + (size_t)wkr * 4096 + wg * 1024 + jbase;
        wv0 = *(const float4*)wp;
        wv1 = *(const float4*)(wp + 4);
        const float* xp = Wo + (size_t)mytok * Dd + xkq * 8;
        xv0 = *(const float4*)xp;
        xv1 = *(const float4*)(xp + 4);
    }
    {
        float wa[8] = {wv0.x,wv0.y,wv0.z,wv0.w,wv1.x,wv1.y,wv1.z,wv1.w};
        #pragma unroll
        for (int j = 0; j < 8; j++) w_sh[0][wg*8 + j][wkr] = wa[j];
        float xa[8] = {xv0.x,xv0.y,xv0.z,xv0.w,xv1.x,xv1.y,xv1.z,xv1.w};
        #pragma unroll
        for (int i = 0; i < 8; i++) x_sh[0][xkq*8 + i][xb] = xa[i];
    }
    __syncthreads();

    int buf = 0;
    for (int ch = 0; ch < 32; ch++) {
        // prefetch next chunk
        if (ch + 1 < 32) {
            int k0 = (ch + 1) * 64;
            if (k0 < 1024) {
                const float* wp = Wx + (size_t)(k0 + wkr) * 4096 + wg * 1024 + jbase;
                wv0 = *(const float4*)wp; wv1 = *(const float4*)(wp + 4);
                const float* xp = Wo + (size_t)mytok * Dd + k0 + xkq * 8;
                xv0 = *(const float4*)xp; xv1 = *(const float4*)(xp + 4);
            } else {
                int kw = k0 - 1024;
                const float* wp = Wh + (size_t)(kw + wkr) * 4096 + wg * 1024 + jbase;
                wv0 = *(const float4*)wp; wv1 = *(const float4*)(wp + 4);
                const float* xp = h_in + xb * Hh + kw + xkq * 8;
                xv0 = *(const float4*)xp; xv1 = *(const float4*)(xp + 4);
            }
        }
        // compute on current buffer: 4 k's per thread (slice + 16*il)
        #pragma unroll
        for (int il = 0; il < 4; il++) {
            int kl = slice + 16 * il;
            ull xp2[4];
            #pragma unroll
            for (int bp = 0; bp < 4; bp++)
                xp2[bp] = *(const ull*)&x_sh[buf][kl][bg*8 + 2*bp];
            #pragma unroll
            for (int cc = 0; cc < 8; cc++) {
                ull ww = dup2(w_sh[buf][cg*8 + cc][kl]);
                #pragma unroll
                for (int bp = 0; bp < 4; bp++)
                    acc[cc][bp] = fma2(xp2[bp], ww, acc[cc][bp]);
            }
        }
        if (ch + 1 < 32) {
            int nb = buf ^ 1;
            float wa[8] = {wv0.x,wv0.y,wv0.z,wv0.w,wv1.x,wv1.y,wv1.z,wv1.w};
            #pragma unroll
            for (int j = 0; j < 8; j++) w_sh[nb][wg*8 + j][wkr] = wa[j];
            float xa[8] = {xv0.x,xv0.y,xv0.z,xv0.w,xv1.x,xv1.y,xv1.z,xv1.w};
            #pragma unroll
            for (int i = 0; i < 8; i++) x_sh[nb][xkq*8 + i][xb] = xa[i];
            __syncthreads();
            buf = nb;
        }
    }
    __syncthreads();   // protect union (red overlays staging)

    // reduce slice pairs within warp (lanes differ in bit0)
    #pragma unroll
    for (int cc = 0; cc < 8; cc++)
        #pragma unroll
        for (int bp = 0; bp < 4; bp++) {
            ull o = __shfl_xor_sync(0xffffffffu, acc[cc][bp], 1);
            acc[cc][bp] = add2(acc[cc][bp], o);
        }
    // even lanes write their tile's 32 ull partials
    if ((lane & 1) == 0) {
        int t = cg * 4 + bg;
        #pragma unroll
        for (int cc = 0; cc < 8; cc++)
            #pragma unroll
            for (int bp = 0; bp < 4; bp++)
                red[warp][t][cc*4 + bp] = acc[cc][bp];
    }
    __syncthreads();

    // final 8-way cross-warp sum: thread handles (tile, 2 ull slots)
    {
        int t = tid >> 4;
        int u2 = (tid & 15) * 2;
        ull s0 = 0ull, s1 = 0ull;
        #pragma unroll
        for (int w = 0; w < 8; w++) {
            s0 = add2(s0, red[w][t][u2]);
            s1 = add2(s1, red[w][t][u2 + 1]);
        }
        int tcg = t >> 2, tbg = t & 3;
        int c0 = u2 >> 2, bp0 = u2 & 3;
        int c1 = (u2 + 1) >> 2, bp1 = (u2 + 1) & 3;
        gate_sh[tcg*8 + c0][tbg*8 + 2*bp0    ] = lo2(s0);
        gate_sh[tcg*8 + c0][tbg*8 + 2*bp0 + 1] = hi2(s0);
        gate_sh[tcg*8 + c1][tbg*8 + 2*bp1    ] = lo2(s1);
        gate_sh[tcg*8 + c1][tbg*8 + 2*bp1 + 1] = hi2(s1);
    }
    __syncthreads();

    {
        int jj = tid >> 5;        // 0..7
        int b  = tid & 31;        // batch
        int J  = jbase + jj;
        float zi = gate_sh[0*8 + jj][b] + bias[J];
        float zf = gate_sh[1*8 + jj][b] + bias[Hh + J];
        float zg = gate_sh[2*8 + jj][b] + bias[2*Hh + J];
        float zo = gate_sh[3*8 + jj][b] + bias[3*Hh + J];
        float cold = c[b * Hh + J];
        float fg = 1.f / (1.f + expf(-(zf + 1.f)));   // forget_bias = 1.0
        float ig = 1.f / (1.f + expf(-zi));
        float og = 1.f / (1.f + expf(-zo));
        float cn = fg * cold + ig * tanhf(zg);
        float hn = og * tanhf(cn);
        c[b * Hh + J] = cn;
        h_out[b * Hh + J] = hn;
    }
}

// ---------------- big teacher-forced logits GEMM (FFMA2) ----------------
__global__ void __launch_bounds__(256, 2) gemm_logits(
    const float* __restrict__ A, const float* __restrict__ Bm, float* __restrict__ C)
{
    __shared__ __align__(16) float As[2][8][128];
    __shared__ __align__(16) float Bs[2][8][128];
    int tid = threadIdx.x;
    int nbase = blockIdx.x * 128;
    int mbase = blockIdx.y * 128;
    int tx = tid & 15, ty = tid >> 4;

    ull acc2[8][4];
    #pragma unroll
    for (int i = 0; i < 8; i++)
        #pragma unroll
        for (int jj = 0; jj < 4; jj++) acc2[i][jj] = 0ull;

    int arow = tid >> 1, akq = (tid & 1) * 4;
    int bk = tid >> 5, bnq = (tid & 31) * 4;
    const float* Aptr = A + (size_t)(mbase + arow) * 1024 + akq;
    const float* Bptr = Bm + (size_t)bk * Vv + nbase + bnq;

    {
        float4 av = *(const float4*)Aptr;
        float4 bv = *(const float4*)Bptr;
        As[0][akq+0][arow] = av.x; As[0][akq+1][arow] = av.y;
        As[0][akq+2][arow] = av.z; As[0][akq+3][arow] = av.w;
        *(float4*)&Bs[0][bk][bnq] = bv;
    }
    __syncthreads();

    int buf = 0;
    for (int k0 = 0; k0 < 1024; k0 += 8) {
        float4 av2, bv2;
        bool has = (k0 + 8) < 1024;
        if (has) {
            av2 = *(const float4*)(Aptr + (k0 + 8));
            bv2 = *(const float4*)(Bptr + (size_t)(k0 + 8) * Vv);
        }
        #pragma unroll
        for (int kk = 0; kk < 8; kk++) {
            float4 a0 = *(const float4*)&As[buf][kk][ty*8];
            float4 a1 = *(const float4*)&As[buf][kk][ty*8 + 4];
            float4 c0 = *(const float4*)&Bs[buf][kk][tx*8];
            float4 c1 = *(const float4*)&Bs[buf][kk][tx*8 + 4];
            ull bw[4];
            bw[0] = pack2(c0.x, c0.y); bw[1] = pack2(c0.z, c0.w);
            bw[2] = pack2(c1.x, c1.y); bw[3] = pack2(c1.z, c1.w);
            float ar[8] = {a0.x,a0.y,a0.z,a0.w,a1.x,a1.y,a1.z,a1.w};
            #pragma unroll
            for (int i = 0; i < 8; i++) {
                ull aw = dup2(ar[i]);
                #pragma unroll
                for (int jj = 0; jj < 4; jj++)
                    acc2[i][jj] = fma2(bw[jj], aw, acc2[i][jj]);
            }
        }
        if (has) {
            int nb = buf ^ 1;
            As[nb][akq+0][arow] = av2.x; As[nb][akq+1][arow] = av2.y;
            As[nb][akq+2][arow] = av2.z; As[nb][akq+3][arow] = av2.w;
            *(float4*)&Bs[nb][bk][bnq] = bv2;
            __syncthreads();
            buf = nb;
        }
    }
    #pragma unroll
    for (int i = 0; i < 8; i++) {
        int row = mbase + ty * 8 + i;
        float* ptr = C + (size_t)row * Vv + nbase + tx * 8;
        float4 o0 = {lo2(acc2[i][0]), hi2(acc2[i][0]), lo2(acc2[i][1]), hi2(acc2[i][1])};
        float4 o1 = {lo2(acc2[i][2]), hi2(acc2[i][2]), lo2(acc2[i][3]), hi2(acc2[i][3])};
        *(float4*)ptr = o0;
        *(float4*)(ptr + 4) = o1;
    }
}

// ---------------- softmax over V per (t,b) row ----------------
__global__ void __launch_bounds__(256) softmax_kernel(
    const float* __restrict__ lg, float* __restrict__ pr)
{
    int row = blockIdx.x;
    const float4* src = (const float4*)(lg + (size_t)row * Vv);
    float4* dst = (float4*)(pr + (size_t)row * Vv);
    const int n4 = Vv / 4;
    int tid = threadIdx.x;

    __shared__ float red[8];
    __shared__ float s_max, s_sum;

    float m = -3.4e38f;
    for (int i = tid; i < n4; i += 256) {
        float4 v = src[i];
        m = fmaxf(m, fmaxf(fmaxf(v.x, v.y), fmaxf(v.z, v.w)));
    }
    #pragma unroll
    for (int o = 16; o; o >>= 1) m = fmaxf(m, __shfl_xor_sync(0xffffffffu, m, o));
    if ((tid & 31) == 0) red[tid >> 5] = m;
    __syncthreads();
    if (tid == 0) {
        float t = red[0];
        #pragma unroll
        for (int i = 1; i < 8; i++) t = fmaxf(t, red[i]);
        s_max = t;
    }
    __syncthreads();
    float rm = s_max;

    float s = 0.f;
    for (int i = tid; i < n4; i += 256) {
        float4 v = src[i];
        s += __expf(v.x - rm) + __expf(v.y - rm) + __expf(v.z - rm) + __expf(v.w - rm);
    }
    #pragma unroll
    for (int o = 16; o; o >>= 1) s += __shfl_xor_sync(0xffffffffu, s, o);
    if ((tid & 31) == 0) red[tid >> 5] = s;
    __syncthreads();
    if (tid == 0) {
        float t = 0.f;
        #pragma unroll
        for (int i = 0; i < 8; i++) t += red[i];
        s_sum = t;
    }
    __syncthreads();
    float inv = 1.f / s_sum;

    for (int i = tid; i < n4; i += 256) {
        float4 v = src[i];
        float4 o;
        o.x = __expf(v.x - rm) * inv; o.y = __expf(v.y - rm) * inv;
        o.z = __expf(v.z - rm) * inv; o.w = __expf(v.w - rm) * inv;
        dst[i] = o;
    }
}

// ---------------- greedy projection v3: lg = h@Wp + argmax ----------------
// 125 blocks x 256 threads. Block: 256 cols x 32 b, K=1024, 2-way split-K.
// Thread tile 8 cols x 8 batches. Warp = 2 slices x 4 cg x 4 bg.
#define PWLP 17
#define PXLP 34
__global__ void __launch_bounds__(256) proj_argmax(
    const float* __restrict__ h, const float* __restrict__ Wp,
    ull* __restrict__ slots)
{
    __shared__ __align__(16) float w_sh[2][256][PWLP];   // transposed [col][k]
    __shared__ __align__(16) float x_sh[2][16][PXLP];
    __shared__ ull red2[8][4][8];

    const int tid = threadIdx.x;
    const int cbase = blockIdx.x * 256;

    // loader indices (w): thread loads 4 float4 from row k0+wkr
    const int wkr = tid >> 4;             // 0..15
    const int wc4 = (tid & 15) * 4;       // col quad base
    // loader indices (x): first 128 threads
    const int xb = tid >> 2;              // 0..31 (if tid<128)
    const int xkq = tid & 3;

    // compute indices
    const int lane = tid & 31, warp = tid >> 5;
    const int slice = lane & 1;
    const int bg = (lane >> 1) & 3;
    const int cg = warp * 4 + (lane >> 3);   // 0..31

    ull acc[8][4];
    #pragma unroll
    for (int i = 0; i < 8; i++)
        #pragma unroll
        for (int j = 0; j < 4; j++) acc[i][j] = 0ull;

    float4 wv[4], xv;

    // prologue chunk 0
    {
        const float* wp = Wp + (size_t)wkr * Vv + cbase + wc4;
        #pragma unroll
        for (int r = 0; r < 4; r++) wv[r] = *(const float4*)(wp + r * 64);
        if (tid < 128) xv = *(const float4*)(h + xb * Hh + xkq * 4);
    }
    {
        #pragma unroll
        for (int r = 0; r < 4; r++) {
            float wa[4] = {wv[r].x, wv[r].y, wv[r].z, wv[r].w};
            #pragma unroll
            for (int j = 0; j < 4; j++)
                w_sh[0][wc4 + r*64 + j][wkr] = wa[j];
        }
        if (tid < 128) {
            x_sh[0][xkq*4+0][xb] = xv.x; x_sh[0][xkq*4+1][xb] = xv.y;
            x_sh[0][xkq*4+2][xb] = xv.z; x_sh[0][xkq*4+3][xb] = xv.w;
        }
    }
    __syncthreads();

    int buf = 0;
    for (int ch = 0; ch < 64; ch++) {
        if (ch + 1 < 64) {
            int k0 = (ch + 1) * 16;
            const float* wp = Wp + (size_t)(k0 + wkr) * Vv + cbase + wc4;
            #pragma unroll
            for (int r = 0; r < 4; r++) wv[r] = *(const float4*)(wp + r * 64);
            if (tid < 128) xv = *(const float4*)(h + xb * Hh + k0 + xkq * 4);
        }
        #pragma unroll
        for (int il = 0; il < 8; il++) {
            int kl = slice + 2 * il;
            ull xp2[4];
            #pragma unroll
            for (int bp = 0; bp < 4; bp++)
                xp2[bp] = *(const ull*)&x_sh[buf][kl][bg*8 + 2*bp];
            #pragma unroll
            for (int cc = 0; cc < 8; cc++) {
                ull ww = dup2(w_sh[buf][cg*8 + cc][kl]);
                #pragma unroll
                for (int bp = 0; bp < 4; bp++)
                    acc[cc][bp] = fma2(xp2[bp], ww, acc[cc][bp]);
            }
        }
        if (ch + 1 < 64) {
            int nb = buf ^ 1;
            #pragma unroll
            for (int r = 0; r < 4; r++) {
                float wa[4] = {wv[r].x, wv[r].y, wv[r].z, wv[r].w};
                #pragma unroll
                for (int j = 0; j < 4; j++)
                    w_sh[nb][wc4 + r*64 + j][wkr] = wa[j];
            }
            if (tid < 128) {
                x_sh[nb][xkq*4+0][xb] = xv.x; x_sh[nb][xkq*4+1][xb] = xv.y;
                x_sh[nb][xkq*4+2][xb] = xv.z; x_sh[nb][xkq*4+3][xb] = xv.w;
            }
            __syncthreads();
            buf = nb;
        }
    }

    // combine the 2 k-slices (adjacent lanes)
    #pragma unroll
    for (int cc = 0; cc < 8; cc++)
        #pragma unroll
        for (int bp = 0; bp < 4; bp++) {
            ull o = __shfl_xor_sync(0xffffffffu, acc[cc][bp], 1);
            acc[cc][bp] = add2(acc[cc][bp], o);
        }

    // per-thread argmax over 8 cols for each of 8 batches
    ull keys[8];
    #pragma unroll
    for (int bp = 0; bp < 4; bp++) {
        ull best_lo = 0ull, best_hi = 0ull;
        #pragma unroll
        for (int cc = 0; cc < 8; cc++) {
            unsigned int colg = cbase + cg * 8 + cc;
            ull klo = ((ull)fkey(lo2(acc[cc][bp])) << 32) | (ull)(0xFFFFFFFFu - colg);
            ull khi = ((ull)fkey(hi2(acc[cc][bp])) << 32) | (ull)(0xFFFFFFFFu - colg);
            if (klo > best_lo) best_lo = klo;
            if (khi > best_hi) best_hi = khi;
        }
        keys[2*bp]     = best_lo;
        keys[2*bp + 1] = best_hi;
    }
    // reduce over col-groups within warp (lane bits 3,4)
    #pragma unroll
    for (int o = 8; o <= 16; o <<= 1) {
        #pragma unroll
        for (int i = 0; i < 8; i++) {
            ull v = __shfl_xor_sync(0xffffffffu, keys[i], o);
            if (v > keys[i]) keys[i] = v;
        }
    }
    if ((lane & 0x19) == 0) {   // slice==0 && cg-local==0  (lane = bg<<1)
        #pragma unroll
        for (int i = 0; i < 8; i++) red2[warp][bg][i] = keys[i];
    }
    __syncthreads();
    if (tid < 32) {
        int b = tid, bbg = b >> 3, bi = b & 7;
        ull m = red2[0][bbg][bi];
        #pragma unroll
        for (int w = 1; w < 8; w++) {
            ull v = red2[w][bbg][bi];
            if (v > m) m = v;
        }
        atomicMax(&slots[b], m);
    }
}

__global__ void final_writer(const ull* __restrict__ slots,
                             float* __restrict__ best_out)
{
    int b = threadIdx.x;
    if (b < 32) {
        ull p = slots[b];
        best_out[b] = (float)(0xFFFFFFFFu - (unsigned int)(p & 0xFFFFFFFFull));
    }
}

// ---------------- host orchestration (graph-capturable) ----------------
extern "C" void kernel_launch(void* const* d_in, const int* in_sizes, int n_in,
                              void* d_out, int out_size)
{
    (void)in_sizes; (void)n_in; (void)out_size;
    const int*   tgt  = (const int*)d_in[0];
    const float* Wo   = (const float*)d_in[1];
    const float* Wx   = (const float*)d_in[2];
    const float* Wh   = (const float*)d_in[3];
    const float* bias = (const float*)d_in[4];
    const float* Wp   = (const float*)d_in[5];

    float* out = (float*)d_out;
    float* out_logits = out;
    float* out_probs  = out + (size_t)Tt * Bx * Vv;
    float* out_best   = out + (size_t)2 * Tt * Bx * Vv;

    float *hs, *zeros, *ctf, *cgr, *hg0, *hg1;
    ull* slots;
    cudaGetSymbolAddress((void**)&hs,    g_hs);
    cudaGetSymbolAddress((void**)&zeros, g_zeros);
    cudaGetSymbolAddress((void**)&ctf,   g_ctf);
    cudaGetSymbolAddress((void**)&cgr,   g_cgr);
    cudaGetSymbolAddress((void**)&hg0,   g_hg0);
    cudaGetSymbolAddress((void**)&hg1,   g_hg1);
    cudaGetSymbolAddress((void**)&slots, g_slots);

    init_kernel<<<(BH + 1023) / 1024, 1024>>>();

    // ---- teacher-forced scan: h_t stored into g_hs[t] ----
    for (int t = 0; t < Tt; t++) {
        lstm_cell<<<128, 256>>>(
            Wx, Wh, bias, Wo,
            tgt + t, Tt, /*mode=*/0,
            nullptr, nullptr, nullptr,
            (t == 0) ? zeros : hs + (size_t)(t - 1) * BH,
            hs + (size_t)t * BH, ctf);
    }

    // ---- logits + softmax ----
    gemm_logits<<<dim3(Vv / 128, (Tt * Bx) / 128), 256>>>(hs, Wp, out_logits);
    softmax_kernel<<<Tt * Bx, 256>>>(out_logits, out_probs);

    // ---- greedy decode ----
    for (int s = 0; s < MX; s++) {
        const float* hi = (s == 0) ? zeros : (((s - 1) & 1) ? hg1 : hg0);
        float* ho = (s & 1) ? hg1 : hg0;
        lstm_cell<<<128, 256>>>(
            Wx, Wh, bias, Wo,
            nullptr, 0, (s == 0) ? 1 : 2,
            (s == 0) ? nullptr : slots + ((s - 1) & 1) * 32,
            slots + (s & 1) * 32,
            (s == 0) ? nullptr : out_best + (size_t)(s - 1) * 32,
            hi, ho, cgr);
        proj_argmax<<<Vv / 256, 256>>>(ho, Wp, slots + (s & 1) * 32);
    }
    final_writer<<<1, 32>>>(slots + ((MX - 1) & 1) * 32,
                            out_best + (size_t)(MX - 1) * 32);
}

// round 5
// speedup vs baseline: 1.3646x; 1.3646x over previous
#include <cuda_runtime.h>
#include <cstdint>
#include <cstddef>

#define Bx 32
#define Tt 64
#define Dd 1024
#define Hh 1024
#define Vv 32000
#define MX 100
#define BH (Bx*Hh)

typedef unsigned long long ull;

// ---------------- device scratch (no allocations allowed) ----------------
__device__ float g_hs[(size_t)Tt*BH];   // teacher-forced hidden states [T][B][H]
__device__ float g_zeros[BH];
__device__ float g_ctf[BH];
__device__ float g_cgr[BH];
__device__ float g_hg0[BH];
__device__ float g_hg1[BH];
__device__ ull g_slots[64];             // two ping-pong buffers of 32
__device__ float g_part[2][Bx][4*Hh];   // split-K partials [khalf][b][gatecol]
__device__ int g_cnt[128];              // per-jblk arrival counters

// ---------------- packed fp32x2 helpers (Blackwell FFMA2) ----------------
__device__ __forceinline__ ull fma2(ull a, ull b, ull c) {
    ull d;
    asm("fma.rn.f32x2 %0, %1, %2, %3;" : "=l"(d) : "l"(a), "l"(b), "l"(c));
    return d;
}
__device__ __forceinline__ ull add2(ull a, ull b) {
    ull d;
    asm("add.rn.f32x2 %0, %1, %2;" : "=l"(d) : "l"(a), "l"(b));
    return d;
}
__device__ __forceinline__ ull dup2(float w) {
    ull d; asm("mov.b64 %0, {%1, %1};" : "=l"(d) : "f"(w)); return d;
}
__device__ __forceinline__ ull pack2(float lo, float hi) {
    ull d; asm("mov.b64 %0, {%1, %2};" : "=l"(d) : "f"(lo), "f"(hi)); return d;
}
__device__ __forceinline__ float lo2(ull v) { return __uint_as_float((unsigned int)(v & 0xFFFFFFFFull)); }
__device__ __forceinline__ float hi2(ull v) { return __uint_as_float((unsigned int)(v >> 32)); }

// ordered-float key: monotonic uint mapping of float
__device__ __forceinline__ unsigned int fkey(float f) {
    unsigned int u = __float_as_uint(f);
    return (u & 0x80000000u) ? ~u : (u | 0x80000000u);
}

__global__ void init_kernel() {
    int i = blockIdx.x * blockDim.x + threadIdx.x;
    if (i < BH) { g_zeros[i] = 0.f; g_ctf[i] = 0.f; g_cgr[i] = 0.f; }
    if (i < 128) g_cnt[i] = 0;
}

// ---------------- fused LSTM cell step v4 ----------------
// 256 blocks x 256 threads, __launch_bounds__(256,2) -> 2 CTAs/SM co-resident.
// Block (jblk, khalf): khalf 0 computes x@Wx half, khalf 1 computes h@Wh half,
// each over 32 (gate,j) cols x 32 batches, K=1024 per block in 16 chunks of 64.
// Inside: v3 layout — 16-way slice split, thread tile 8 cols x 8 batches,
// w_sh transposed [col][k] pitch 65; x_sh [k][b] pitch 34 (conflict-free).
// Cross-block combine: STG partial -> fence -> counter; 2nd arriver finishes.
#define WLP 65
#define XLP 34
#define SB_W  16640            // [2][32][65] floats
#define SB_X  17408            // [2][64][34] floats
__global__ void __launch_bounds__(256, 2) lstm_cell(
    const float* __restrict__ Wx, const float* __restrict__ Wh,
    const float* __restrict__ bias, const float* __restrict__ Wo,
    const int* __restrict__ tok_src, int tok_stride, int mode,
    const ull* __restrict__ slots_in,
    ull* __restrict__ slots_reset,
    float* __restrict__ best_prev_out,
    const float* __restrict__ h_in, float* __restrict__ h_out,
    float* __restrict__ c)
{
    __shared__ __align__(16) char sbuf[SB_W + SB_X];   // union: staging | red
    float (*w_sh)[32][WLP] = (float (*)[32][WLP])sbuf;
    float (*x_sh)[64][XLP] = (float (*)[64][XLP])(sbuf + SB_W);
    ull   (*red)[16][32]   = (ull (*)[16][32])sbuf;    // [8][16][32] = 32KB
    __shared__ float gate_sh[32][33];
    __shared__ int tok_sh[32];
    __shared__ int is_finisher;

    const int tid   = threadIdx.x;
    const int jblk  = blockIdx.x & 127;
    const int khalf = blockIdx.x >> 7;
    const int jbase = jblk * 8;

    if (khalf == 0) {
        if (tid < 32) {
            int tk;
            if (mode == 0) tk = tok_src[tid * tok_stride];
            else if (mode == 1) tk = 1;  // GO token
            else {
                ull p = slots_in[tid];
                tk = (int)(0xFFFFFFFFu - (unsigned int)(p & 0xFFFFFFFFull));
                if (blockIdx.x == 0 && best_prev_out) best_prev_out[tid] = (float)tk;
            }
            tok_sh[tid] = tk;
            if (blockIdx.x == 0 && slots_reset) slots_reset[tid] = 0ull;
        }
        __syncthreads();
    }

    // loader indices
    const int wkr = tid >> 2;          // 0..63 : w row within chunk
    const int wg  = tid & 3;           // gate for w loader
    const int xb  = tid >> 3;          // 0..31 : batch for x loader
    const int xkq = tid & 7;           // k-octet for x loader
    const float* Wbase = khalf ? Wh : Wx;
    const float* xbase = khalf ? (h_in + xb * Hh)
                               : (Wo + (size_t)tok_sh[xb] * Dd);

    // compute indices
    const int lane = tid & 31, warp = tid >> 5;
    const int slice = 2 * warp + (lane & 1);   // 0..15
    const int bg = (lane >> 1) & 3;            // batch group
    const int cg = lane >> 3;                  // col group == gate

    ull acc[8][4];
    #pragma unroll
    for (int i = 0; i < 8; i++)
        #pragma unroll
        for (int j = 0; j < 4; j++) acc[i][j] = 0ull;

    float4 wv0, wv1, xv0, xv1;

    // prologue: load chunk 0
    {
        const float* wp = Wbase + (size_t)wkr * 4096 + wg * 1024 + jbase;
        wv0 = *(const float4*)wp;
        wv1 = *(const float4*)(wp + 4);
        const float* xp = xbase + xkq * 8;
        xv0 = *(const float4*)xp;
        xv1 = *(const float4*)(xp + 4);
    }
    {
        float wa[8] = {wv0.x,wv0.y,wv0.z,wv0.w,wv1.x,wv1.y,wv1.z,wv1.w};
        #pragma unroll
        for (int j = 0; j < 8; j++) w_sh[0][wg*8 + j][wkr] = wa[j];
        float xa[8] = {xv0.x,xv0.y,xv0.z,xv0.w,xv1.x,xv1.y,xv1.z,xv1.w};
        #pragma unroll
        for (int i = 0; i < 8; i++) x_sh[0][xkq*8 + i][xb] = xa[i];
    }
    __syncthreads();

    int buf = 0;
    for (int ch = 0; ch < 16; ch++) {
        // prefetch next chunk
        if (ch + 1 < 16) {
            int k0 = (ch + 1) * 64;
            const float* wp = Wbase + (size_t)(k0 + wkr) * 4096 + wg * 1024 + jbase;
            wv0 = *(const float4*)wp; wv1 = *(const float4*)(wp + 4);
            const float* xp = xbase + k0 + xkq * 8;
            xv0 = *(const float4*)xp; xv1 = *(const float4*)(xp + 4);
        }
        // compute on current buffer: 4 k's per thread (slice + 16*il)
        #pragma unroll
        for (int il = 0; il < 4; il++) {
            int kl = slice + 16 * il;
            ull xp2[4];
            #pragma unroll
            for (int bp = 0; bp < 4; bp++)
                xp2[bp] = *(const ull*)&x_sh[buf][kl][bg*8 + 2*bp];
            #pragma unroll
            for (int cc = 0; cc < 8; cc++) {
                ull ww = dup2(w_sh[buf][cg*8 + cc][kl]);
                #pragma unroll
                for (int bp = 0; bp < 4; bp++)
                    acc[cc][bp] = fma2(xp2[bp], ww, acc[cc][bp]);
            }
        }
        if (ch + 1 < 16) {
            int nb = buf ^ 1;
            float wa[8] = {wv0.x,wv0.y,wv0.z,wv0.w,wv1.x,wv1.y,wv1.z,wv1.w};
            #pragma unroll
            for (int j = 0; j < 8; j++) w_sh[nb][wg*8 + j][wkr] = wa[j];
            float xa[8] = {xv0.x,xv0.y,xv0.z,xv0.w,xv1.x,xv1.y,xv1.z,xv1.w};
            #pragma unroll
            for (int i = 0; i < 8; i++) x_sh[nb][xkq*8 + i][xb] = xa[i];
            __syncthreads();
            buf = nb;
        }
    }
    __syncthreads();   // protect union (red overlays staging)

    // reduce slice pairs within warp (lanes differ in bit0)
    #pragma unroll
    for (int cc = 0; cc < 8; cc++)
        #pragma unroll
        for (int bp = 0; bp < 4; bp++) {
            ull o = __shfl_xor_sync(0xffffffffu, acc[cc][bp], 1);
            acc[cc][bp] = add2(acc[cc][bp], o);
        }
    // even lanes write their tile's 32 ull partials
    if ((lane & 1) == 0) {
        int t = cg * 4 + bg;
        #pragma unroll
        for (int cc = 0; cc < 8; cc++)
            #pragma unroll
            for (int bp = 0; bp < 4; bp++)
                red[warp][t][cc*4 + bp] = acc[cc][bp];
    }
    __syncthreads();

    // final 8-way cross-warp sum into gate_sh
    {
        int t = tid >> 4;
        int u2 = (tid & 15) * 2;
        ull s0 = 0ull, s1 = 0ull;
        #pragma unroll
        for (int w = 0; w < 8; w++) {
            s0 = add2(s0, red[w][t][u2]);
            s1 = add2(s1, red[w][t][u2 + 1]);
        }
        int tcg = t >> 2, tbg = t & 3;
        int c0 = u2 >> 2, bp0 = u2 & 3;
        int c1 = (u2 + 1) >> 2, bp1 = (u2 + 1) & 3;
        gate_sh[tcg*8 + c0][tbg*8 + 2*bp0    ] = lo2(s0);
        gate_sh[tcg*8 + c0][tbg*8 + 2*bp0 + 1] = hi2(s0);
        gate_sh[tcg*8 + c1][tbg*8 + 2*bp1    ] = lo2(s1);
        gate_sh[tcg*8 + c1][tbg*8 + 2*bp1 + 1] = hi2(s1);
    }
    __syncthreads();

    // publish this block's partial: thread (jj,b) stores all 4 gates
    {
        int jj = tid >> 5, b = tid & 31;
        int J = jbase + jj;
        #pragma unroll
        for (int g = 0; g < 4; g++)
            g_part[khalf][b][g * Hh + J] = gate_sh[g*8 + jj][b];
    }
    __threadfence();
    if (tid == 0) {
        int old = atomicAdd(&g_cnt[jblk], 1);
        is_finisher = (old == 1);
    }
    __syncthreads();
    if (!is_finisher) return;
    __threadfence();   // acquire partner's partial

    {
        int jj = tid >> 5;        // 0..7
        int b  = tid & 31;        // batch
        int J  = jbase + jj;
        int ph = 1 - khalf;
        float zi = gate_sh[0*8 + jj][b] + __ldcg(&g_part[ph][b][          J]) + bias[J];
        float zf = gate_sh[1*8 + jj][b] + __ldcg(&g_part[ph][b][  Hh +    J]) + bias[Hh + J];
        float zg = gate_sh[2*8 + jj][b] + __ldcg(&g_part[ph][b][2*Hh +    J]) + bias[2*Hh + J];
        float zo = gate_sh[3*8 + jj][b] + __ldcg(&g_part[ph][b][3*Hh +    J]) + bias[3*Hh + J];
        float cold = c[b * Hh + J];
        float fg = 1.f / (1.f + expf(-(zf + 1.f)));   // forget_bias = 1.0
        float ig = 1.f / (1.f + expf(-zi));
        float og = 1.f / (1.f + expf(-zo));
        float cn = fg * cold + ig * tanhf(zg);
        float hn = og * tanhf(cn);
        c[b * Hh + J] = cn;
        h_out[b * Hh + J] = hn;
    }
    if (tid == 0) g_cnt[jblk] = 0;   // reset for next launch (stream-ordered)
}

// ---------------- big teacher-forced logits GEMM (FFMA2) ----------------
__global__ void __launch_bounds__(256, 2) gemm_logits(
    const float* __restrict__ A, const float* __restrict__ Bm, float* __restrict__ C)
{
    __shared__ __align__(16) float As[2][8][128];
    __shared__ __align__(16) float Bs[2][8][128];
    int tid = threadIdx.x;
    int nbase = blockIdx.x * 128;
    int mbase = blockIdx.y * 128;
    int tx = tid & 15, ty = tid >> 4;

    ull acc2[8][4];
    #pragma unroll
    for (int i = 0; i < 8; i++)
        #pragma unroll
        for (int jj = 0; jj < 4; jj++) acc2[i][jj] = 0ull;

    int arow = tid >> 1, akq = (tid & 1) * 4;
    int bk = tid >> 5, bnq = (tid & 31) * 4;
    const float* Aptr = A + (size_t)(mbase + arow) * 1024 + akq;
    const float* Bptr = Bm + (size_t)bk * Vv + nbase + bnq;

    {
        float4 av = *(const float4*)Aptr;
        float4 bv = *(const float4*)Bptr;
        As[0][akq+0][arow] = av.x; As[0][akq+1][arow] = av.y;
        As[0][akq+2][arow] = av.z; As[0][akq+3][arow] = av.w;
        *(float4*)&Bs[0][bk][bnq] = bv;
    }
    __syncthreads();

    int buf = 0;
    for (int k0 = 0; k0 < 1024; k0 += 8) {
        float4 av2, bv2;
        bool has = (k0 + 8) < 1024;
        if (has) {
            av2 = *(const float4*)(Aptr + (k0 + 8));
            bv2 = *(const float4*)(Bptr + (size_t)(k0 + 8) * Vv);
        }
        #pragma unroll
        for (int kk = 0; kk < 8; kk++) {
            float4 a0 = *(const float4*)&As[buf][kk][ty*8];
            float4 a1 = *(const float4*)&As[buf][kk][ty*8 + 4];
            float4 c0 = *(const float4*)&Bs[buf][kk][tx*8];
            float4 c1 = *(const float4*)&Bs[buf][kk][tx*8 + 4];
            ull bw[4];
            bw[0] = pack2(c0.x, c0.y); bw[1] = pack2(c0.z, c0.w);
            bw[2] = pack2(c1.x, c1.y); bw[3] = pack2(c1.z, c1.w);
            float ar[8] = {a0.x,a0.y,a0.z,a0.w,a1.x,a1.y,a1.z,a1.w};
            #pragma unroll
            for (int i = 0; i < 8; i++) {
                ull aw = dup2(ar[i]);
                #pragma unroll
                for (int jj = 0; jj < 4; jj++)
                    acc2[i][jj] = fma2(bw[jj], aw, acc2[i][jj]);
            }
        }
        if (has) {
            int nb = buf ^ 1;
            As[nb][akq+0][arow] = av2.x; As[nb][akq+1][arow] = av2.y;
            As[nb][akq+2][arow] = av2.z; As[nb][akq+3][arow] = av2.w;
            *(float4*)&Bs[nb][bk][bnq] = bv2;
            __syncthreads();
            buf = nb;
        }
    }
    #pragma unroll
    for (int i = 0; i < 8; i++) {
        int row = mbase + ty * 8 + i;
        float* ptr = C + (size_t)row * Vv + nbase + tx * 8;
        float4 o0 = {lo2(acc2[i][0]), hi2(acc2[i][0]), lo2(acc2[i][1]), hi2(acc2[i][1])};
        float4 o1 = {lo2(acc2[i][2]), hi2(acc2[i][2]), lo2(acc2[i][3]), hi2(acc2[i][3])};
        *(float4*)ptr = o0;
        *(float4*)(ptr + 4) = o1;
    }
}

// ---------------- softmax over V per (t,b) row ----------------
__global__ void __launch_bounds__(256) softmax_kernel(
    const float* __restrict__ lg, float* __restrict__ pr)
{
    int row = blockIdx.x;
    const float4* src = (const float4*)(lg + (size_t)row * Vv);
    float4* dst = (float4*)(pr + (size_t)row * Vv);
    const int n4 = Vv / 4;
    int tid = threadIdx.x;

    __shared__ float red[8];
    __shared__ float s_max, s_sum;

    float m = -3.4e38f;
    for (int i = tid; i < n4; i += 256) {
        float4 v = src[i];
        m = fmaxf(m, fmaxf(fmaxf(v.x, v.y), fmaxf(v.z, v.w)));
    }
    #pragma unroll
    for (int o = 16; o; o >>= 1) m = fmaxf(m, __shfl_xor_sync(0xffffffffu, m, o));
    if ((tid & 31) == 0) red[tid >> 5] = m;
    __syncthreads();
    if (tid == 0) {
        float t = red[0];
        #pragma unroll
        for (int i = 1; i < 8; i++) t = fmaxf(t, red[i]);
        s_max = t;
    }
    __syncthreads();
    float rm = s_max;

    float s = 0.f;
    for (int i = tid; i < n4; i += 256) {
        float4 v = src[i];
        s += __expf(v.x - rm) + __expf(v.y - rm) + __expf(v.z - rm) + __expf(v.w - rm);
    }
    #pragma unroll
    for (int o = 16; o; o >>= 1) s += __shfl_xor_sync(0xffffffffu, s, o);
    if ((tid & 31) == 0) red[tid >> 5] = s;
    __syncthreads();
    if (tid == 0) {
        float t = 0.f;
        #pragma unroll
        for (int i = 0; i < 8; i++) t += red[i];
        s_sum = t;
    }
    __syncthreads();
    float inv = 1.f / s_sum;

    for (int i = tid; i < n4; i += 256) {
        float4 v = src[i];
        float4 o;
        o.x = __expf(v.x - rm) * inv; o.y = __expf(v.y - rm) * inv;
        o.z = __expf(v.z - rm) * inv; o.w = __expf(v.w - rm) * inv;
        dst[i] = o;
    }
}

// ---------------- greedy projection (v2, proven): lg = h@Wp + argmax ------
// grid 125 blocks x 256 cols; thread = (4 cols x 8 batches). smem-staged W + x.
__global__ void __launch_bounds__(256) proj_argmax(
    const float* __restrict__ h, const float* __restrict__ Wp,
    ull* __restrict__ slots)
{
    __shared__ __align__(16) float w_sh[2][16][256];
    __shared__ __align__(16) float x_sh[2][16][36];
    __shared__ ull wred[8][8];

    const int tid = threadIdx.x;
    const int cbase = blockIdx.x * 256;

    // staging indices
    const int kr = tid >> 6;          // 0..3  (W rows kr, kr+4, kr+8, kr+12)
    const int c4 = (tid & 63) * 4;    // W col quad
    const int sb = tid >> 2;          // 0..63 (x batch; only <32 active)
    const int skq = tid & 3;          // x k-quad

    // compute indices
    const int cg = tid & 63;          // col group (4 cols)
    const int b0 = (tid >> 6) * 8;    // batch group (8 batches)

    ull acc2[4][4];
    #pragma unroll
    for (int i = 0; i < 4; i++)
        #pragma unroll
        for (int jj = 0; jj < 4; jj++) acc2[i][jj] = 0ull;

    float4 wr0, wr1, wr2, wr3, xr;

    // prologue: chunk 0
    {
        const float* wp = Wp + cbase + c4;
        wr0 = *(const float4*)(wp + (size_t)(kr     ) * Vv);
        wr1 = *(const float4*)(wp + (size_t)(kr +  4) * Vv);
        wr2 = *(const float4*)(wp + (size_t)(kr +  8) * Vv);
        wr3 = *(const float4*)(wp + (size_t)(kr + 12) * Vv);
        if (sb < 32) xr = *(const float4*)(h + sb * Hh + skq * 4);
    }
    *(float4*)&w_sh[0][kr     ][c4] = wr0;
    *(float4*)&w_sh[0][kr +  4][c4] = wr1;
    *(float4*)&w_sh[0][kr +  8][c4] = wr2;
    *(float4*)&w_sh[0][kr + 12][c4] = wr3;
    if (sb < 32) {
        x_sh[0][skq*4+0][sb] = xr.x; x_sh[0][skq*4+1][sb] = xr.y;
        x_sh[0][skq*4+2][sb] = xr.z; x_sh[0][skq*4+3][sb] = xr.w;
    }
    __syncthreads();

    int buf = 0;
    for (int ch = 0; ch < 64; ch++) {
        if (ch + 1 < 64) {
            int k0 = (ch + 1) * 16;
            const float* wp = Wp + (size_t)k0 * Vv + cbase + c4;
            wr0 = *(const float4*)(wp + (size_t)(kr     ) * Vv);
            wr1 = *(const float4*)(wp + (size_t)(kr +  4) * Vv);
            wr2 = *(const float4*)(wp + (size_t)(kr +  8) * Vv);
            wr3 = *(const float4*)(wp + (size_t)(kr + 12) * Vv);
            if (sb < 32) xr = *(const float4*)(h + sb * Hh + k0 + skq * 4);
        }
        #pragma unroll
        for (int kk = 0; kk < 16; kk++) {
            float4 w4 = *(const float4*)&w_sh[buf][kk][cg * 4];
            float4 xa = *(const float4*)&x_sh[buf][kk][b0];
            float4 xb4 = *(const float4*)&x_sh[buf][kk][b0 + 4];
            ull x01 = pack2(xa.x, xa.y),  x23 = pack2(xa.z, xa.w);
            ull x45 = pack2(xb4.x, xb4.y), x67 = pack2(xb4.z, xb4.w);
            float wf[4] = {w4.x, w4.y, w4.z, w4.w};
            #pragma unroll
            for (int cc = 0; cc < 4; cc++) {
                ull ww = dup2(wf[cc]);
                acc2[cc][0] = fma2(x01, ww, acc2[cc][0]);
                acc2[cc][1] = fma2(x23, ww, acc2[cc][1]);
                acc2[cc][2] = fma2(x45, ww, acc2[cc][2]);
                acc2[cc][3] = fma2(x67, ww, acc2[cc][3]);
            }
        }
        if (ch + 1 < 64) {
            int nb = buf ^ 1;
            *(float4*)&w_sh[nb][kr     ][c4] = wr0;
            *(float4*)&w_sh[nb][kr +  4][c4] = wr1;
            *(float4*)&w_sh[nb][kr +  8][c4] = wr2;
            *(float4*)&w_sh[nb][kr + 12][c4] = wr3;
            if (sb < 32) {
                x_sh[nb][skq*4+0][sb] = xr.x; x_sh[nb][skq*4+1][sb] = xr.y;
                x_sh[nb][skq*4+2][sb] = xr.z; x_sh[nb][skq*4+3][sb] = xr.w;
            }
            __syncthreads();
            buf = nb;
        }
    }

    // per-thread best over its 4 cols, for each of 8 batches; then warp reduce.
    ull pk[8];
    #pragma unroll
    for (int i = 0; i < 8; i++) {
        int p = i >> 1;
        ull best = 0ull;
        #pragma unroll
        for (int cc = 0; cc < 4; cc++) {
            float v = (i & 1) ? hi2(acc2[cc][p]) : lo2(acc2[cc][p]);
            unsigned int colg = cbase + cg * 4 + cc;
            ull pkv = ((ull)fkey(v) << 32) | (ull)(0xFFFFFFFFu - colg);
            if (pkv > best) best = pkv;
        }
        pk[i] = best;
    }
    #pragma unroll
    for (int o = 16; o; o >>= 1) {
        #pragma unroll
        for (int i = 0; i < 8; i++) {
            ull other = __shfl_xor_sync(0xffffffffu, pk[i], o);
            if (other > pk[i]) pk[i] = other;
        }
    }
    int w = tid >> 5;
    if ((tid & 31) == 0) {
        #pragma unroll
        for (int i = 0; i < 8; i++) wred[w][i] = pk[i];
    }
    __syncthreads();
    if (tid < 32) {
        int b = tid, bg = b >> 3, bi = b & 7;
        ull m0 = wred[bg * 2][bi];
        ull m1 = wred[bg * 2 + 1][bi];
        if (m1 > m0) m0 = m1;
        atomicMax(&slots[b], m0);
    }
}

__global__ void final_writer(const ull* __restrict__ slots,
                             float* __restrict__ best_out)
{
    int b = threadIdx.x;
    if (b < 32) {
        ull p = slots[b];
        best_out[b] = (float)(0xFFFFFFFFu - (unsigned int)(p & 0xFFFFFFFFull));
    }
}

// ---------------- host orchestration (graph-capturable) ----------------
extern "C" void kernel_launch(void* const* d_in, const int* in_sizes, int n_in,
                              void* d_out, int out_size)
{
    (void)in_sizes; (void)n_in; (void)out_size;
    const int*   tgt  = (const int*)d_in[0];
    const float* Wo   = (const float*)d_in[1];
    const float* Wx   = (const float*)d_in[2];
    const float* Wh   = (const float*)d_in[3];
    const float* bias = (const float*)d_in[4];
    const float* Wp   = (const float*)d_in[5];

    float* out = (float*)d_out;
    float* out_logits = out;
    float* out_probs  = out + (size_t)Tt * Bx * Vv;
    float* out_best   = out + (size_t)2 * Tt * Bx * Vv;

    float *hs, *zeros, *ctf, *cgr, *hg0, *hg1;
    ull* slots;
    cudaGetSymbolAddress((void**)&hs,    g_hs);
    cudaGetSymbolAddress((void**)&zeros, g_zeros);
    cudaGetSymbolAddress((void**)&ctf,   g_ctf);
    cudaGetSymbolAddress((void**)&cgr,   g_cgr);
    cudaGetSymbolAddress((void**)&hg0,   g_hg0);
    cudaGetSymbolAddress((void**)&hg1,   g_hg1);
    cudaGetSymbolAddress((void**)&slots, g_slots);

    init_kernel<<<(BH + 1023) / 1024, 1024>>>();

    // ---- teacher-forced scan: h_t stored into g_hs[t] ----
    for (int t = 0; t < Tt; t++) {
        lstm_cell<<<256, 256>>>(
            Wx, Wh, bias, Wo,
            tgt + t, Tt, /*mode=*/0,
            nullptr, nullptr, nullptr,
            (t == 0) ? zeros : hs + (size_t)(t - 1) * BH,
            hs + (size_t)t * BH, ctf);
    }

    // ---- logits + softmax ----
    gemm_logits<<<dim3(Vv / 128, (Tt * Bx) / 128), 256>>>(hs, Wp, out_logits);
    softmax_kernel<<<Tt * Bx, 256>>>(out_logits, out_probs);

    // ---- greedy decode ----
    for (int s = 0; s < MX; s++) {
        const float* hi = (s == 0) ? zeros : (((s - 1) & 1) ? hg1 : hg0);
        float* ho = (s & 1) ? hg1 : hg0;
        lstm_cell<<<256, 256>>>(
            Wx, Wh, bias, Wo,
            nullptr, 0, (s == 0) ? 1 : 2,
            (s == 0) ? nullptr : slots + ((s - 1) & 1) * 32,
            slots + (s & 1) * 32,
            (s == 0) ? nullptr : out_best + (size_t)(s - 1) * 32,
            hi, ho, cgr);
        proj_argmax<<<Vv / 256, 256>>>(ho, Wp, slots + (s & 1) * 32);
    }
    final_writer<<<1, 32>>>(slots + ((MX - 1) & 1) * 32,
                            out_best + (size_t)(MX - 1) * 32);
}

// round 7
// speedup vs baseline: 1.4811x; 1.0854x over previous
#include <cuda_runtime.h>
#include <cstdint>
#include <cstddef>

#define Bx 32
#define Tt 64
#define Dd 1024
#define Hh 1024
#define Vv 32000
#define MX 100
#define BH (Bx*Hh)

typedef unsigned long long ull;

// ---------------- device scratch (no allocations allowed) ----------------
__device__ float g_hs[(size_t)Tt*BH];   // teacher-forced hidden states [T][B][H]
__device__ float g_zx[(size_t)Tt*Bx*4*Hh]; // precomputed x@Wx for TF, row r=t*32+b
__device__ float g_zeros[BH];
__device__ float g_ctf[BH];
__device__ float g_cgr[BH];
__device__ float g_hg0[BH];
__device__ float g_hg1[BH];
__device__ ull g_slots[64];             // two ping-pong buffers of 32
__device__ float g_part[2][Bx][4*Hh];   // split-K partials [khalf][b][gatecol]
__device__ int g_cnt[128];              // per-jblk arrival counters

// ---------------- packed fp32x2 helpers (Blackwell FFMA2) ----------------
__device__ __forceinline__ ull fma2(ull a, ull b, ull c) {
    ull d;
    asm("fma.rn.f32x2 %0, %1, %2, %3;" : "=l"(d) : "l"(a), "l"(b), "l"(c));
    return d;
}
__device__ __forceinline__ ull add2(ull a, ull b) {
    ull d;
    asm("add.rn.f32x2 %0, %1, %2;" : "=l"(d) : "l"(a), "l"(b));
    return d;
}
__device__ __forceinline__ ull dup2(float w) {
    ull d; asm("mov.b64 %0, {%1, %1};" : "=l"(d) : "f"(w)); return d;
}
__device__ __forceinline__ ull pack2(float lo, float hi) {
    ull d; asm("mov.b64 %0, {%1, %2};" : "=l"(d) : "f"(lo), "f"(hi)); return d;
}
__device__ __forceinline__ float lo2(ull v) { return __uint_as_float((unsigned int)(v & 0xFFFFFFFFull)); }
__device__ __forceinline__ float hi2(ull v) { return __uint_as_float((unsigned int)(v >> 32)); }

// ordered-float key: monotonic uint mapping of float
__device__ __forceinline__ unsigned int fkey(float f) {
    unsigned int u = __float_as_uint(f);
    return (u & 0x80000000u) ? ~u : (u | 0x80000000u);
}

__global__ void init_kernel() {
    int i = blockIdx.x * blockDim.x + threadIdx.x;
    if (i < BH) { g_zeros[i] = 0.f; g_ctf[i] = 0.f; g_cgr[i] = 0.f; }
    if (i < 128) g_cnt[i] = 0;
}

// ---------------- fused LSTM cell step v5 ----------------
// Unified: zx != nullptr -> TF mode: grid 128, single half (h@Wh), finish with
// precomputed zx.  zx == nullptr -> greedy mode: grid 256, two halves + counter.
// Inner: w_sh[k][col] pitch 36 (LDS.128/STS.128), x_sh[k][b] pitch 34 (LDS.64).
// 16-way slice split-K within block, thread tile 8 cols x 8 batches.
#define WP 36
#define XLP 34
#define SB_W  18432            // [2][64][36] floats
#define SB_X  17408            // [2][64][34] floats
__global__ void __launch_bounds__(256, 2) lstm_cell(
    const float* __restrict__ Wx, const float* __restrict__ Wh,
    const float* __restrict__ bias, const float* __restrict__ Wo,
    const int* __restrict__ tok_src, int tok_stride, int mode,
    const ull* __restrict__ slots_in,
    ull* __restrict__ slots_reset,
    float* __restrict__ best_prev_out,
    const float* __restrict__ h_in, float* __restrict__ h_out,
    float* __restrict__ c, const float* __restrict__ zx)
{
    __shared__ __align__(16) char sbuf[SB_W + SB_X];   // union: staging | red
    float (*w_sh)[64][WP]  = (float (*)[64][WP])sbuf;
    float (*x_sh)[64][XLP] = (float (*)[64][XLP])(sbuf + SB_W);
    ull   (*red)[16][32]   = (ull (*)[16][32])sbuf;    // [8][16][32] = 32KB
    __shared__ float gate_sh[32][33];
    __shared__ int tok_sh[32];
    __shared__ int is_finisher;

    const int tid = threadIdx.x;
    const bool two_half = (zx == nullptr);
    const int jblk  = two_half ? (blockIdx.x & 127) : blockIdx.x;
    const int khalf = two_half ? (blockIdx.x >> 7) : 1;
    const int jbase = jblk * 8;

    if (two_half && khalf == 0) {
        if (tid < 32) {
            int tk;
            if (mode == 0) tk = tok_src[tid * tok_stride];
            else if (mode == 1) tk = 1;  // GO token
            else {
                ull p = slots_in[tid];
                tk = (int)(0xFFFFFFFFu - (unsigned int)(p & 0xFFFFFFFFull));
                if (blockIdx.x == 0 && best_prev_out) best_prev_out[tid] = (float)tk;
            }
            tok_sh[tid] = tk;
            if (blockIdx.x == 0 && slots_reset) slots_reset[tid] = 0ull;
        }
        __syncthreads();
    }

    // loader indices
    const int wkr = tid >> 2;          // 0..63 : w row within chunk
    const int wg  = tid & 3;           // gate for w loader
    const int xb  = tid >> 3;          // 0..31 : batch for x loader
    const int xkq = tid & 7;           // k-octet for x loader
    const float* Wbase = khalf ? Wh : Wx;
    const float* xbase = khalf ? (h_in + xb * Hh)
                               : (Wo + (size_t)tok_sh[xb] * Dd);

    // compute indices
    const int lane = tid & 31, warp = tid >> 5;
    const int slice = 2 * warp + (lane & 1);   // 0..15
    const int bg = (lane >> 1) & 3;            // batch group
    const int cg = lane >> 3;                  // col group == gate

    ull acc[8][4];
    #pragma unroll
    for (int i = 0; i < 8; i++)
        #pragma unroll
        for (int j = 0; j < 4; j++) acc[i][j] = 0ull;

    float4 wv0, wv1, xv0, xv1;

    // prologue: load chunk 0
    {
        const float* wp = Wbase + (size_t)wkr * 4096 + wg * 1024 + jbase;
        wv0 = *(const float4*)wp;
        wv1 = *(const float4*)(wp + 4);
        const float* xp = xbase + xkq * 8;
        xv0 = *(const float4*)xp;
        xv1 = *(const float4*)(xp + 4);
    }
    {
        *(float4*)&w_sh[0][wkr][wg*8]     = wv0;
        *(float4*)&w_sh[0][wkr][wg*8 + 4] = wv1;
        float xa[8] = {xv0.x,xv0.y,xv0.z,xv0.w,xv1.x,xv1.y,xv1.z,xv1.w};
        #pragma unroll
        for (int i = 0; i < 8; i++) x_sh[0][xkq*8 + i][xb] = xa[i];
    }
    __syncthreads();

    int buf = 0;
    for (int ch = 0; ch < 16; ch++) {
        // prefetch next chunk
        if (ch + 1 < 16) {
            int k0 = (ch + 1) * 64;
            const float* wp = Wbase + (size_t)(k0 + wkr) * 4096 + wg * 1024 + jbase;
            wv0 = *(const float4*)wp; wv1 = *(const float4*)(wp + 4);
            const float* xp = xbase + k0 + xkq * 8;
            xv0 = *(const float4*)xp; xv1 = *(const float4*)(xp + 4);
        }
        // compute on current buffer: 4 k's per thread (slice + 16*il)
        #pragma unroll
        for (int il = 0; il < 4; il++) {
            int kl = slice + 16 * il;
            ull xp2[4];
            #pragma unroll
            for (int bp = 0; bp < 4; bp++)
                xp2[bp] = *(const ull*)&x_sh[buf][kl][bg*8 + 2*bp];
            float4 wa = *(const float4*)&w_sh[buf][kl][cg*8];
            float4 wb = *(const float4*)&w_sh[buf][kl][cg*8 + 4];
            float wf[8] = {wa.x,wa.y,wa.z,wa.w,wb.x,wb.y,wb.z,wb.w};
            #pragma unroll
            for (int cc = 0; cc < 8; cc++) {
                ull ww = dup2(wf[cc]);
                #pragma unroll
                for (int bp = 0; bp < 4; bp++)
                    acc[cc][bp] = fma2(xp2[bp], ww, acc[cc][bp]);
            }
        }
        if (ch + 1 < 16) {
            int nb = buf ^ 1;
            *(float4*)&w_sh[nb][wkr][wg*8]     = wv0;
            *(float4*)&w_sh[nb][wkr][wg*8 + 4] = wv1;
            float xa[8] = {xv0.x,xv0.y,xv0.z,xv0.w,xv1.x,xv1.y,xv1.z,xv1.w};
            #pragma unroll
            for (int i = 0; i < 8; i++) x_sh[nb][xkq*8 + i][xb] = xa[i];
            __syncthreads();
            buf = nb;
        }
    }
    __syncthreads();   // protect union (red overlays staging)

    // reduce slice pairs within warp (lanes differ in bit0)
    #pragma unroll
    for (int cc = 0; cc < 8; cc++)
        #pragma unroll
        for (int bp = 0; bp < 4; bp++) {
            ull o = __shfl_xor_sync(0xffffffffu, acc[cc][bp], 1);
            acc[cc][bp] = add2(acc[cc][bp], o);
        }
    // even lanes write their tile's 32 ull partials
    if ((lane & 1) == 0) {
        int t = cg * 4 + bg;
        #pragma unroll
        for (int cc = 0; cc < 8; cc++)
            #pragma unroll
            for (int bp = 0; bp < 4; bp++)
                red[warp][t][cc*4 + bp] = acc[cc][bp];
    }
    __syncthreads();

    // final 8-way cross-warp sum into gate_sh
    {
        int t = tid >> 4;
        int u2 = (tid & 15) * 2;
        ull s0 = 0ull, s1 = 0ull;
        #pragma unroll
        for (int w = 0; w < 8; w++) {
            s0 = add2(s0, red[w][t][u2]);
            s1 = add2(s1, red[w][t][u2 + 1]);
        }
        int tcg = t >> 2, tbg = t & 3;
        int c0 = u2 >> 2, bp0 = u2 & 3;
        int c1 = (u2 + 1) >> 2, bp1 = (u2 + 1) & 3;
        gate_sh[tcg*8 + c0][tbg*8 + 2*bp0    ] = lo2(s0);
        gate_sh[tcg*8 + c0][tbg*8 + 2*bp0 + 1] = hi2(s0);
        gate_sh[tcg*8 + c1][tbg*8 + 2*bp1    ] = lo2(s1);
        gate_sh[tcg*8 + c1][tbg*8 + 2*bp1 + 1] = hi2(s1);
    }
    __syncthreads();

    if (!two_half) {
        // TF mode: finish directly with precomputed zx (row = b within step)
        int jj = tid >> 5, b = tid & 31;
        int J = jbase + jj;
        const float* zr = zx + (size_t)b * 4096;
        float zi = gate_sh[0*8 + jj][b] + zr[          J] + bias[J];
        float zf = gate_sh[1*8 + jj][b] + zr[  Hh +    J] + bias[Hh + J];
        float zg = gate_sh[2*8 + jj][b] + zr[2*Hh +    J] + bias[2*Hh + J];
        float zo = gate_sh[3*8 + jj][b] + zr[3*Hh +    J] + bias[3*Hh + J];
        float cold = c[b * Hh + J];
        float fg = 1.f / (1.f + expf(-(zf + 1.f)));
        float ig = 1.f / (1.f + expf(-zi));
        float og = 1.f / (1.f + expf(-zo));
        float cn = fg * cold + ig * tanhf(zg);
        float hn = og * tanhf(cn);
        c[b * Hh + J] = cn;
        h_out[b * Hh + J] = hn;
        return;
    }

    // greedy mode: publish partial, second arriver finishes
    {
        int jj = tid >> 5, b = tid & 31;
        int J = jbase + jj;
        #pragma unroll
        for (int g = 0; g < 4; g++)
            g_part[khalf][b][g * Hh + J] = gate_sh[g*8 + jj][b];
    }
    __threadfence();
    if (tid == 0) {
        int old = atomicAdd(&g_cnt[jblk], 1);
        is_finisher = (old == 1);
    }
    __syncthreads();
    if (!is_finisher) return;
    __threadfence();   // acquire partner's partial

    {
        int jj = tid >> 5;
        int b  = tid & 31;
        int J  = jbase + jj;
        int ph = 1 - khalf;
        float zi = gate_sh[0*8 + jj][b] + __ldcg(&g_part[ph][b][          J]) + bias[J];
        float zf = gate_sh[1*8 + jj][b] + __ldcg(&g_part[ph][b][  Hh +    J]) + bias[Hh + J];
        float zg = gate_sh[2*8 + jj][b] + __ldcg(&g_part[ph][b][2*Hh +    J]) + bias[2*Hh + J];
        float zo = gate_sh[3*8 + jj][b] + __ldcg(&g_part[ph][b][3*Hh +    J]) + bias[3*Hh + J];
        float cold = c[b * Hh + J];
        float fg = 1.f / (1.f + expf(-(zf + 1.f)));
        float ig = 1.f / (1.f + expf(-zi));
        float og = 1.f / (1.f + expf(-zo));
        float cn = fg * cold + ig * tanhf(zg);
        float hn = og * tanhf(cn);
        c[b * Hh + J] = cn;
        h_out[b * Hh + J] = hn;
    }
    if (tid == 0) g_cnt[jblk] = 0;   // reset for next launch (stream-ordered)
}

// ---------------- ZX = gather(Wo, tgt) @ Wx  (TF input hoist) ----------------
// C[2048, 4096], A row r = t*32+b -> Wo[tgt[b*Tt+t]], K=1024. 128x128x8 tiles.
__global__ void __launch_bounds__(256, 2) gemm_zx(
    const int* __restrict__ tgt, const float* __restrict__ Wo,
    const float* __restrict__ Wx, float* __restrict__ C)
{
    __shared__ __align__(16) float As[2][8][128];
    __shared__ __align__(16) float Bs[2][8][128];
    int tid = threadIdx.x;
    int nbase = blockIdx.x * 128;
    int mbase = blockIdx.y * 128;
    int tx = tid & 15, ty = tid >> 4;

    ull acc2[8][4];
    #pragma unroll
    for (int i = 0; i < 8; i++)
        #pragma unroll
        for (int jj = 0; jj < 4; jj++) acc2[i][jj] = 0ull;

    int arow = tid >> 1, akq = (tid & 1) * 4;
    int r = mbase + arow;
    int tok = tgt[(r & 31) * Tt + (r >> 5)];
    int bk = tid >> 5, bnq = (tid & 31) * 4;
    const float* Aptr = Wo + (size_t)tok * Dd + akq;
    const float* Bptr = Wx + (size_t)bk * 4096 + nbase + bnq;

    {
        float4 av = *(const float4*)Aptr;
        float4 bv = *(const float4*)Bptr;
        As[0][akq+0][arow] = av.x; As[0][akq+1][arow] = av.y;
        As[0][akq+2][arow] = av.z; As[0][akq+3][arow] = av.w;
        *(float4*)&Bs[0][bk][bnq] = bv;
    }
    __syncthreads();

    int buf = 0;
    for (int k0 = 0; k0 < 1024; k0 += 8) {
        float4 av2, bv2;
        bool has = (k0 + 8) < 1024;
        if (has) {
            av2 = *(const float4*)(Aptr + (k0 + 8));
            bv2 = *(const float4*)(Bptr + (size_t)(k0 + 8) * 4096);
        }
        #pragma unroll
        for (int kk = 0; kk < 8; kk++) {
            float4 a0 = *(const float4*)&As[buf][kk][ty*8];
            float4 a1 = *(const float4*)&As[buf][kk][ty*8 + 4];
            float4 c0 = *(const float4*)&Bs[buf][kk][tx*8];
            float4 c1 = *(const float4*)&Bs[buf][kk][tx*8 + 4];
            ull bw[4];
            bw[0] = pack2(c0.x, c0.y); bw[1] = pack2(c0.z, c0.w);
            bw[2] = pack2(c1.x, c1.y); bw[3] = pack2(c1.z, c1.w);
            float ar[8] = {a0.x,a0.y,a0.z,a0.w,a1.x,a1.y,a1.z,a1.w};
            #pragma unroll
            for (int i = 0; i < 8; i++) {
                ull aw = dup2(ar[i]);
                #pragma unroll
                for (int jj = 0; jj < 4; jj++)
                    acc2[i][jj] = fma2(bw[jj], aw, acc2[i][jj]);
            }
        }
        if (has) {
            int nb = buf ^ 1;
            As[nb][akq+0][arow] = av2.x; As[nb][akq+1][arow] = av2.y;
            As[nb][akq+2][arow] = av2.z; As[nb][akq+3][arow] = av2.w;
            *(float4*)&Bs[nb][bk][bnq] = bv2;
            __syncthreads();
            buf = nb;
        }
    }
    #pragma unroll
    for (int i = 0; i < 8; i++) {
        int row = mbase + ty * 8 + i;
        float* ptr = C + (size_t)row * 4096 + nbase + tx * 8;
        float4 o0 = {lo2(acc2[i][0]), hi2(acc2[i][0]), lo2(acc2[i][1]), hi2(acc2[i][1])};
        float4 o1 = {lo2(acc2[i][2]), hi2(acc2[i][2]), lo2(acc2[i][3]), hi2(acc2[i][3])};
        *(float4*)ptr = o0;
        *(float4*)(ptr + 4) = o1;
    }
}

// ---------------- big teacher-forced logits GEMM (FFMA2) ----------------
__global__ void __launch_bounds__(256, 2) gemm_logits(
    const float* __restrict__ A, const float* __restrict__ Bm, float* __restrict__ C)
{
    __shared__ __align__(16) float As[2][8][128];
    __shared__ __align__(16) float Bs[2][8][128];
    int tid = threadIdx.x;
    int nbase = blockIdx.x * 128;
    int mbase = blockIdx.y * 128;
    int tx = tid & 15, ty = tid >> 4;

    ull acc2[8][4];
    #pragma unroll
    for (int i = 0; i < 8; i++)
        #pragma unroll
        for (int jj = 0; jj < 4; jj++) acc2[i][jj] = 0ull;

    int arow = tid >> 1, akq = (tid & 1) * 4;
    int bk = tid >> 5, bnq = (tid & 31) * 4;
    const float* Aptr = A + (size_t)(mbase + arow) * 1024 + akq;
    const float* Bptr = Bm + (size_t)bk * Vv + nbase + bnq;

    {
        float4 av = *(const float4*)Aptr;
        float4 bv = *(const float4*)Bptr;
        As[0][akq+0][arow] = av.x; As[0][akq+1][arow] = av.y;
        As[0][akq+2][arow] = av.z; As[0][akq+3][arow] = av.w;
        *(float4*)&Bs[0][bk][bnq] = bv;
    }
    __syncthreads();

    int buf = 0;
    for (int k0 = 0; k0 < 1024; k0 += 8) {
        float4 av2, bv2;
        bool has = (k0 + 8) < 1024;
        if (has) {
            av2 = *(const float4*)(Aptr + (k0 + 8));
            bv2 = *(const float4*)(Bptr + (size_t)(k0 + 8) * Vv);
        }
        #pragma unroll
        for (int kk = 0; kk < 8; kk++) {
            float4 a0 = *(const float4*)&As[buf][kk][ty*8];
            float4 a1 = *(const float4*)&As[buf][kk][ty*8 + 4];
            float4 c0 = *(const float4*)&Bs[buf][kk][tx*8];
            float4 c1 = *(const float4*)&Bs[buf][kk][tx*8 + 4];
            ull bw[4];
            bw[0] = pack2(c0.x, c0.y); bw[1] = pack2(c0.z, c0.w);
            bw[2] = pack2(c1.x, c1.y); bw[3] = pack2(c1.z, c1.w);
            float ar[8] = {a0.x,a0.y,a0.z,a0.w,a1.x,a1.y,a1.z,a1.w};
            #pragma unroll
            for (int i = 0; i < 8; i++) {
                ull aw = dup2(ar[i]);
                #pragma unroll
                for (int jj = 0; jj < 4; jj++)
                    acc2[i][jj] = fma2(bw[jj], aw, acc2[i][jj]);
            }
        }
        if (has) {
            int nb = buf ^ 1;
            As[nb][akq+0][arow] = av2.x; As[nb][akq+1][arow] = av2.y;
            As[nb][akq+2][arow] = av2.z; As[nb][akq+3][arow] = av2.w;
            *(float4*)&Bs[nb][bk][bnq] = bv2;
            __syncthreads();
            buf = nb;
        }
    }
    #pragma unroll
    for (int i = 0; i < 8; i++) {
        int row = mbase + ty * 8 + i;
        float* ptr = C + (size_t)row * Vv + nbase + tx * 8;
        float4 o0 = {lo2(acc2[i][0]), hi2(acc2[i][0]), lo2(acc2[i][1]), hi2(acc2[i][1])};
        float4 o1 = {lo2(acc2[i][2]), hi2(acc2[i][2]), lo2(acc2[i][3]), hi2(acc2[i][3])};
        *(float4*)ptr = o0;
        *(float4*)(ptr + 4) = o1;
    }
}

// ---------------- softmax over V per (t,b) row ----------------
__global__ void __launch_bounds__(256) softmax_kernel(
    const float* __restrict__ lg, float* __restrict__ pr)
{
    int row = blockIdx.x;
    const float4* src = (const float4*)(lg + (size_t)row * Vv);
    float4* dst = (float4*)(pr + (size_t)row * Vv);
    const int n4 = Vv / 4;
    int tid = threadIdx.x;

    __shared__ float red[8];
    __shared__ float s_max, s_sum;

    float m = -3.4e38f;
    for (int i = tid; i < n4; i += 256) {
        float4 v = src[i];
        m = fmaxf(m, fmaxf(fmaxf(v.x, v.y), fmaxf(v.z, v.w)));
    }
    #pragma unroll
    for (int o = 16; o; o >>= 1) m = fmaxf(m, __shfl_xor_sync(0xffffffffu, m, o));
    if ((tid & 31) == 0) red[tid >> 5] = m;
    __syncthreads();
    if (tid == 0) {
        float t = red[0];
        #pragma unroll
        for (int i = 1; i < 8; i++) t = fmaxf(t, red[i]);
        s_max = t;
    }
    __syncthreads();
    float rm = s_max;

    float s = 0.f;
    for (int i = tid; i < n4; i += 256) {
        float4 v = src[i];
        s += __expf(v.x - rm) + __expf(v.y - rm) + __expf(v.z - rm) + __expf(v.w - rm);
    }
    #pragma unroll
    for (int o = 16; o; o >>= 1) s += __shfl_xor_sync(0xffffffffu, s, o);
    if ((tid & 31) == 0) red[tid >> 5] = s;
    __syncthreads();
    if (tid == 0) {
        float t = 0.f;
        #pragma unroll
        for (int i = 0; i < 8; i++) t += red[i];
        s_sum = t;
    }
    __syncthreads();
    float inv = 1.f / s_sum;

    for (int i = tid; i < n4; i += 256) {
        float4 v = src[i];
        float4 o;
        o.x = __expf(v.x - rm) * inv; o.y = __expf(v.y - rm) * inv;
        o.z = __expf(v.z - rm) * inv; o.w = __expf(v.w - rm) * inv;
        dst[i] = o;
    }
}

// ---------------- greedy projection (v2, proven): lg = h@Wp + argmax ------
__global__ void __launch_bounds__(256) proj_argmax(
    const float* __restrict__ h, const float* __restrict__ Wp,
    ull* __restrict__ slots)
{
    __shared__ __align__(16) float w_sh[2][16][256];
    __shared__ __align__(16) float x_sh[2][16][36];
    __shared__ ull wred[8][8];

    const int tid = threadIdx.x;
    const int cbase = blockIdx.x * 256;

    const int kr = tid >> 6;
    const int c4 = (tid & 63) * 4;
    const int sb = tid >> 2;
    const int skq = tid & 3;

    const int cg = tid & 63;
    const int b0 = (tid >> 6) * 8;

    ull acc2[4][4];
    #pragma unroll
    for (int i = 0; i < 4; i++)
        #pragma unroll
        for (int jj = 0; jj < 4; jj++) acc2[i][jj] = 0ull;

    float4 wr0, wr1, wr2, wr3, xr;

    {
        const float* wp = Wp + cbase + c4;
        wr0 = *(const float4*)(wp + (size_t)(kr     ) * Vv);
        wr1 = *(const float4*)(wp + (size_t)(kr +  4) * Vv);
        wr2 = *(const float4*)(wp + (size_t)(kr +  8) * Vv);
        wr3 = *(const float4*)(wp + (size_t)(kr + 12) * Vv);
        if (sb < 32) xr = *(const float4*)(h + sb * Hh + skq * 4);
    }
    *(float4*)&w_sh[0][kr     ][c4] = wr0;
    *(float4*)&w_sh[0][kr +  4][c4] = wr1;
    *(float4*)&w_sh[0][kr +  8][c4] = wr2;
    *(float4*)&w_sh[0][kr + 12][c4] = wr3;
    if (sb < 32) {
        x_sh[0][skq*4+0][sb] = xr.x; x_sh[0][skq*4+1][sb] = xr.y;
        x_sh[0][skq*4+2][sb] = xr.z; x_sh[0][skq*4+3][sb] = xr.w;
    }
    __syncthreads();

    int buf = 0;
    for (int ch = 0; ch < 64; ch++) {
        if (ch + 1 < 64) {
            int k0 = (ch + 1) * 16;
            const float* wp = Wp + (size_t)k0 * Vv + cbase + c4;
            wr0 = *(const float4*)(wp + (size_t)(kr     ) * Vv);
            wr1 = *(const float4*)(wp + (size_t)(kr +  4) * Vv);
            wr2 = *(const float4*)(wp + (size_t)(kr +  8) * Vv);
            wr3 = *(const float4*)(wp + (size_t)(kr + 12) * Vv);
            if (sb < 32) xr = *(const float4*)(h + sb * Hh + k0 + skq * 4);
        }
        #pragma unroll
        for (int kk = 0; kk < 16; kk++) {
            float4 w4 = *(const float4*)&w_sh[buf][kk][cg * 4];
            float4 xa = *(const float4*)&x_sh[buf][kk][b0];
            float4 xb4 = *(const float4*)&x_sh[buf][kk][b0 + 4];
            ull x01 = pack2(xa.x, xa.y),  x23 = pack2(xa.z, xa.w);
            ull x45 = pack2(xb4.x, xb4.y), x67 = pack2(xb4.z, xb4.w);
            float wf[4] = {w4.x, w4.y, w4.z, w4.w};
            #pragma unroll
            for (int cc = 0; cc < 4; cc++) {
                ull ww = dup2(wf[cc]);
                acc2[cc][0] = fma2(x01, ww, acc2[cc][0]);
                acc2[cc][1] = fma2(x23, ww, acc2[cc][1]);
                acc2[cc][2] = fma2(x45, ww, acc2[cc][2]);
                acc2[cc][3] = fma2(x67, ww, acc2[cc][3]);
            }
        }
        if (ch + 1 < 64) {
            int nb = buf ^ 1;
            *(float4*)&w_sh[nb][kr     ][c4] = wr0;
            *(float4*)&w_sh[nb][kr +  4][c4] = wr1;
            *(float4*)&w_sh[nb][kr +  8][c4] = wr2;
            *(float4*)&w_sh[nb][kr + 12][c4] = wr3;
            if (sb < 32) {
                x_sh[nb][skq*4+0][sb] = xr.x; x_sh[nb][skq*4+1][sb] = xr.y;
                x_sh[nb][skq*4+2][sb] = xr.z; x_sh[nb][skq*4+3][sb] = xr.w;
            }
            __syncthreads();
            buf = nb;
        }
    }

    ull pk[8];
    #pragma unroll
    for (int i = 0; i < 8; i++) {
        int p = i >> 1;
        ull best = 0ull;
        #pragma unroll
        for (int cc = 0; cc < 4; cc++) {
            float v = (i & 1) ? hi2(acc2[cc][p]) : lo2(acc2[cc][p]);
            unsigned int colg = cbase + cg * 4 + cc;
            ull pkv = ((ull)fkey(v) << 32) | (ull)(0xFFFFFFFFu - colg);
            if (pkv > best) best = pkv;
        }
        pk[i] = best;
    }
    #pragma unroll
    for (int o = 16; o; o >>= 1) {
        #pragma unroll
        for (int i = 0; i < 8; i++) {
            ull other = __shfl_xor_sync(0xffffffffu, pk[i], o);
            if (other > pk[i]) pk[i] = other;
        }
    }
    int w = tid >> 5;
    if ((tid & 31) == 0) {
        #pragma unroll
        for (int i = 0; i < 8; i++) wred[w][i] = pk[i];
    }
    __syncthreads();
    if (tid < 32) {
        int b = tid, bg = b >> 3, bi = b & 7;
        ull m0 = wred[bg * 2][bi];
        ull m1 = wred[bg * 2 + 1][bi];
        if (m1 > m0) m0 = m1;
        atomicMax(&slots[b], m0);
    }
}

__global__ void final_writer(const ull* __restrict__ slots,
                             float* __restrict__ best_out)
{
    int b = threadIdx.x;
    if (b < 32) {
        ull p = slots[b];
        best_out[b] = (float)(0xFFFFFFFFu - (unsigned int)(p & 0xFFFFFFFFull));
    }
}

// ---------------- host orchestration (graph-capturable) ----------------
extern "C" void kernel_launch(void* const* d_in, const int* in_sizes, int n_in,
                              void* d_out, int out_size)
{
    (void)in_sizes; (void)n_in; (void)out_size;
    const int*   tgt  = (const int*)d_in[0];
    const float* Wo   = (const float*)d_in[1];
    const float* Wx   = (const float*)d_in[2];
    const float* Wh   = (const float*)d_in[3];
    const float* bias = (const float*)d_in[4];
    const float* Wp   = (const float*)d_in[5];

    float* out = (float*)d_out;
    float* out_logits = out;
    float* out_probs  = out + (size_t)Tt * Bx * Vv;
    float* out_best   = out + (size_t)2 * Tt * Bx * Vv;

    float *hs, *zxb, *zeros, *ctf, *cgr, *hg0, *hg1;
    ull* slots;
    cudaGetSymbolAddress((void**)&hs,    g_hs);
    cudaGetSymbolAddress((void**)&zxb,   g_zx);
    cudaGetSymbolAddress((void**)&zeros, g_zeros);
    cudaGetSymbolAddress((void**)&ctf,   g_ctf);
    cudaGetSymbolAddress((void**)&cgr,   g_cgr);
    cudaGetSymbolAddress((void**)&hg0,   g_hg0);
    cudaGetSymbolAddress((void**)&hg1,   g_hg1);
    cudaGetSymbolAddress((void**)&slots, g_slots);

    init_kernel<<<(BH + 1023) / 1024, 1024>>>();

    // ---- hoisted TF input projection: ZX = gather(Wo,tgt) @ Wx ----
    gemm_zx<<<dim3(4096 / 128, (Tt * Bx) / 128), 256>>>(tgt, Wo, Wx, zxb);

    // ---- teacher-forced scan: h_t stored into g_hs[t] ----
    for (int t = 0; t < Tt; t++) {
        lstm_cell<<<128, 256>>>(
            Wx, Wh, bias, Wo,
            nullptr, 0, /*mode=*/3,
            nullptr, nullptr, nullptr,
            (t == 0) ? zeros : hs + (size_t)(t - 1) * BH,
            hs + (size_t)t * BH, ctf,
            zxb + (size_t)t * Bx * 4096);
    }

    // ---- logits + softmax ----
    gemm_logits<<<dim3(Vv / 128, (Tt * Bx) / 128), 256>>>(hs, Wp, out_logits);
    softmax_kernel<<<Tt * Bx, 256>>>(out_logits, out_probs);

    // ---- greedy decode ----
    for (int s = 0; s < MX; s++) {
        const float* hi = (s == 0) ? zeros : (((s - 1) & 1) ? hg1 : hg0);
        float* ho = (s & 1) ? hg1 : hg0;
        lstm_cell<<<256, 256>>>(
            Wx, Wh, bias, Wo,
            nullptr, 0, (s == 0) ? 1 : 2,
            (s == 0) ? nullptr : slots + ((s - 1) & 1) * 32,
            slots + (s & 1) * 32,
            (s == 0) ? nullptr : out_best + (size_t)(s - 1) * 32,
            hi, ho, cgr, nullptr);
        proj_argmax<<<Vv / 256, 256>>>(ho, Wp, slots + (s & 1) * 32);
    }
    final_writer<<<1, 32>>>(slots + ((MX - 1) & 1) * 32,
                            out_best + (size_t)(MX - 1) * 32);
}

// round 8
// speedup vs baseline: 1.6557x; 1.1179x over previous
#include <cuda_runtime.h>
#include <cstdint>
#include <cstddef>

#define Bx 32
#define Tt 64
#define Dd 1024
#define Hh 1024
#define Vv 32000
#define MX 100
#define BH (Bx*Hh)

typedef unsigned long long ull;
typedef unsigned int uint32;

// ---------------- device scratch (no allocations allowed) ----------------
__device__ float g_hs[(size_t)Tt*BH];   // teacher-forced hidden states [T][B][H]
__device__ float g_zx[(size_t)Tt*Bx*4*Hh]; // precomputed x@Wx for TF
__device__ float g_zeros[BH];
__device__ float g_ctf[BH];
__device__ float g_cgr[BH];
__device__ float g_hg0[BH];
__device__ float g_hg1[BH];
__device__ ull g_slots[64];             // two ping-pong buffers of 32
__device__ float g_part[2][Bx][4*Hh];   // split-K partials [khalf][b][gatecol]
__device__ int g_cnt[128];              // per-jblk arrival counters
// bf16-split copies (packed bf16x2 per uint: element 2i low half, 2i+1 high)
__device__ uint32 g_hsh[(size_t)Tt*Bx*Hh/2];
__device__ uint32 g_hsl[(size_t)Tt*Bx*Hh/2];
__device__ uint32 g_wph[(size_t)Dd*Vv/2];
__device__ uint32 g_wpl[(size_t)Dd*Vv/2];

// ---------------- packed fp32x2 helpers (Blackwell FFMA2) ----------------
__device__ __forceinline__ ull fma2(ull a, ull b, ull c) {
    ull d;
    asm("fma.rn.f32x2 %0, %1, %2, %3;" : "=l"(d) : "l"(a), "l"(b), "l"(c));
    return d;
}
__device__ __forceinline__ ull add2(ull a, ull b) {
    ull d;
    asm("add.rn.f32x2 %0, %1, %2;" : "=l"(d) : "l"(a), "l"(b));
    return d;
}
__device__ __forceinline__ ull dup2(float w) {
    ull d; asm("mov.b64 %0, {%1, %1};" : "=l"(d) : "f"(w)); return d;
}
__device__ __forceinline__ ull pack2(float lo, float hi) {
    ull d; asm("mov.b64 %0, {%1, %2};" : "=l"(d) : "f"(lo), "f"(hi)); return d;
}
__device__ __forceinline__ float lo2(ull v) { return __uint_as_float((unsigned int)(v & 0xFFFFFFFFull)); }
__device__ __forceinline__ float hi2(ull v) { return __uint_as_float((unsigned int)(v >> 32)); }

// ---------------- bf16 pack/unpack helpers ----------------
__device__ __forceinline__ uint32 pkbf(float lo, float hi) {
    uint32 r;
    asm("cvt.rn.bf16x2.f32 %0, %1, %2;" : "=r"(r) : "f"(hi), "f"(lo));
    return r;
}
__device__ __forceinline__ float bflo(uint32 u) { return __uint_as_float(u << 16); }
__device__ __forceinline__ float bfhi(uint32 u) { return __uint_as_float(u & 0xFFFF0000u); }

__device__ __forceinline__ uint32 smem_u32(const void* p) {
    uint32 a;
    asm("{ .reg .u64 t; cvta.to.shared.u64 t, %1; cvt.u32.u64 %0, t; }" : "=r"(a) : "l"(p));
    return a;
}

#define LDSM_X4(r, addr) \
    asm volatile("ldmatrix.sync.aligned.m8n8.x4.shared.b16 {%0,%1,%2,%3}, [%4];" \
        : "=r"((r)[0]), "=r"((r)[1]), "=r"((r)[2]), "=r"((r)[3]) : "r"(addr))
#define LDSM_X4T(r, addr) \
    asm volatile("ldmatrix.sync.aligned.m8n8.x4.trans.shared.b16 {%0,%1,%2,%3}, [%4];" \
        : "=r"((r)[0]), "=r"((r)[1]), "=r"((r)[2]), "=r"((r)[3]) : "r"(addr))
#define MMA_BF16(d, a, b0, b1) \
    asm volatile("mma.sync.aligned.m16n8k16.row.col.f32.bf16.bf16.f32 " \
        "{%0,%1,%2,%3}, {%4,%5,%6,%7}, {%8,%9}, {%0,%1,%2,%3};" \
        : "+f"((d)[0]), "+f"((d)[1]), "+f"((d)[2]), "+f"((d)[3]) \
        : "r"((a)[0]), "r"((a)[1]), "r"((a)[2]), "r"((a)[3]), "r"(b0), "r"(b1))

// ordered-float key: monotonic uint mapping of float
__device__ __forceinline__ unsigned int fkey(float f) {
    unsigned int u = __float_as_uint(f);
    return (u & 0x80000000u) ? ~u : (u | 0x80000000u);
}

__global__ void init_kernel() {
    int i = blockIdx.x * blockDim.x + threadIdx.x;
    if (i < BH) { g_zeros[i] = 0.f; g_ctf[i] = 0.f; g_cgr[i] = 0.f; }
    if (i < 128) g_cnt[i] = 0;
}

// ---------------- fp32 -> bf16 hi/lo split (elementwise, float4 = 2 pairs) ----
__global__ void __launch_bounds__(1024) conv_split4(
    const float4* __restrict__ src, uint2* __restrict__ dh, uint2* __restrict__ dl, int n4)
{
    int i = blockIdx.x * blockDim.x + threadIdx.x;
    if (i < n4) {
        float4 v = src[i];
        uint32 h0 = pkbf(v.x, v.y), h1 = pkbf(v.z, v.w);
        uint32 l0 = pkbf(v.x - bflo(h0), v.y - bfhi(h0));
        uint32 l1 = pkbf(v.z - bflo(h1), v.w - bfhi(h1));
        dh[i] = make_uint2(h0, h1);
        dl[i] = make_uint2(l0, l1);
    }
}

// ---------------- fused LSTM cell step v5 (proven R7) ----------------
#define WP 36
#define XLP 34
#define SB_W  18432            // [2][64][36] floats
#define SB_X  17408            // [2][64][34] floats
__global__ void __launch_bounds__(256, 2) lstm_cell(
    const float* __restrict__ Wx, const float* __restrict__ Wh,
    const float* __restrict__ bias, const float* __restrict__ Wo,
    const int* __restrict__ tok_src, int tok_stride, int mode,
    const ull* __restrict__ slots_in,
    ull* __restrict__ slots_reset,
    float* __restrict__ best_prev_out,
    const float* __restrict__ h_in, float* __restrict__ h_out,
    float* __restrict__ c, const float* __restrict__ zx)
{
    __shared__ __align__(16) char sbuf[SB_W + SB_X];   // union: staging | red
    float (*w_sh)[64][WP]  = (float (*)[64][WP])sbuf;
    float (*x_sh)[64][XLP] = (float (*)[64][XLP])(sbuf + SB_W);
    ull   (*red)[16][32]   = (ull (*)[16][32])sbuf;    // [8][16][32] = 32KB
    __shared__ float gate_sh[32][33];
    __shared__ int tok_sh[32];
    __shared__ int is_finisher;

    const int tid = threadIdx.x;
    const bool two_half = (zx == nullptr);
    const int jblk  = two_half ? (blockIdx.x & 127) : blockIdx.x;
    const int khalf = two_half ? (blockIdx.x >> 7) : 1;
    const int jbase = jblk * 8;

    if (two_half && khalf == 0) {
        if (tid < 32) {
            int tk;
            if (mode == 0) tk = tok_src[tid * tok_stride];
            else if (mode == 1) tk = 1;  // GO token
            else {
                ull p = slots_in[tid];
                tk = (int)(0xFFFFFFFFu - (unsigned int)(p & 0xFFFFFFFFull));
                if (blockIdx.x == 0 && best_prev_out) best_prev_out[tid] = (float)tk;
            }
            tok_sh[tid] = tk;
            if (blockIdx.x == 0 && slots_reset) slots_reset[tid] = 0ull;
        }
        __syncthreads();
    }

    const int wkr = tid >> 2;
    const int wg  = tid & 3;
    const int xb  = tid >> 3;
    const int xkq = tid & 7;
    const float* Wbase = khalf ? Wh : Wx;
    const float* xbase = khalf ? (h_in + xb * Hh)
                               : (Wo + (size_t)tok_sh[xb] * Dd);

    const int lane = tid & 31, warp = tid >> 5;
    const int slice = 2 * warp + (lane & 1);
    const int bg = (lane >> 1) & 3;
    const int cg = lane >> 3;

    ull acc[8][4];
    #pragma unroll
    for (int i = 0; i < 8; i++)
        #pragma unroll
        for (int j = 0; j < 4; j++) acc[i][j] = 0ull;

    float4 wv0, wv1, xv0, xv1;

    {
        const float* wp = Wbase + (size_t)wkr * 4096 + wg * 1024 + jbase;
        wv0 = *(const float4*)wp;
        wv1 = *(const float4*)(wp + 4);
        const float* xp = xbase + xkq * 8;
        xv0 = *(const float4*)xp;
        xv1 = *(const float4*)(xp + 4);
    }
    {
        *(float4*)&w_sh[0][wkr][wg*8]     = wv0;
        *(float4*)&w_sh[0][wkr][wg*8 + 4] = wv1;
        float xa[8] = {xv0.x,xv0.y,xv0.z,xv0.w,xv1.x,xv1.y,xv1.z,xv1.w};
        #pragma unroll
        for (int i = 0; i < 8; i++) x_sh[0][xkq*8 + i][xb] = xa[i];
    }
    __syncthreads();

    int buf = 0;
    for (int ch = 0; ch < 16; ch++) {
        if (ch + 1 < 16) {
            int k0 = (ch + 1) * 64;
            const float* wp = Wbase + (size_t)(k0 + wkr) * 4096 + wg * 1024 + jbase;
            wv0 = *(const float4*)wp; wv1 = *(const float4*)(wp + 4);
            const float* xp = xbase + k0 + xkq * 8;
            xv0 = *(const float4*)xp; xv1 = *(const float4*)(xp + 4);
        }
        #pragma unroll
        for (int il = 0; il < 4; il++) {
            int kl = slice + 16 * il;
            ull xp2[4];
            #pragma unroll
            for (int bp = 0; bp < 4; bp++)
                xp2[bp] = *(const ull*)&x_sh[buf][kl][bg*8 + 2*bp];
            float4 wa = *(const float4*)&w_sh[buf][kl][cg*8];
            float4 wb = *(const float4*)&w_sh[buf][kl][cg*8 + 4];
            float wf[8] = {wa.x,wa.y,wa.z,wa.w,wb.x,wb.y,wb.z,wb.w};
            #pragma unroll
            for (int cc = 0; cc < 8; cc++) {
                ull ww = dup2(wf[cc]);
                #pragma unroll
                for (int bp = 0; bp < 4; bp++)
                    acc[cc][bp] = fma2(xp2[bp], ww, acc[cc][bp]);
            }
        }
        if (ch + 1 < 16) {
            int nb = buf ^ 1;
            *(float4*)&w_sh[nb][wkr][wg*8]     = wv0;
            *(float4*)&w_sh[nb][wkr][wg*8 + 4] = wv1;
            float xa[8] = {xv0.x,xv0.y,xv0.z,xv0.w,xv1.x,xv1.y,xv1.z,xv1.w};
            #pragma unroll
            for (int i = 0; i < 8; i++) x_sh[nb][xkq*8 + i][xb] = xa[i];
            __syncthreads();
            buf = nb;
        }
    }
    __syncthreads();

    #pragma unroll
    for (int cc = 0; cc < 8; cc++)
        #pragma unroll
        for (int bp = 0; bp < 4; bp++) {
            ull o = __shfl_xor_sync(0xffffffffu, acc[cc][bp], 1);
            acc[cc][bp] = add2(acc[cc][bp], o);
        }
    if ((lane & 1) == 0) {
        int t = cg * 4 + bg;
        #pragma unroll
        for (int cc = 0; cc < 8; cc++)
            #pragma unroll
            for (int bp = 0; bp < 4; bp++)
                red[warp][t][cc*4 + bp] = acc[cc][bp];
    }
    __syncthreads();

    {
        int t = tid >> 4;
        int u2 = (tid & 15) * 2;
        ull s0 = 0ull, s1 = 0ull;
        #pragma unroll
        for (int w = 0; w < 8; w++) {
            s0 = add2(s0, red[w][t][u2]);
            s1 = add2(s1, red[w][t][u2 + 1]);
        }
        int tcg = t >> 2, tbg = t & 3;
        int c0 = u2 >> 2, bp0 = u2 & 3;
        int c1 = (u2 + 1) >> 2, bp1 = (u2 + 1) & 3;
        gate_sh[tcg*8 + c0][tbg*8 + 2*bp0    ] = lo2(s0);
        gate_sh[tcg*8 + c0][tbg*8 + 2*bp0 + 1] = hi2(s0);
        gate_sh[tcg*8 + c1][tbg*8 + 2*bp1    ] = lo2(s1);
        gate_sh[tcg*8 + c1][tbg*8 + 2*bp1 + 1] = hi2(s1);
    }
    __syncthreads();

    if (!two_half) {
        int jj = tid >> 5, b = tid & 31;
        int J = jbase + jj;
        const float* zr = zx + (size_t)b * 4096;
        float zi = gate_sh[0*8 + jj][b] + zr[          J] + bias[J];
        float zf = gate_sh[1*8 + jj][b] + zr[  Hh +    J] + bias[Hh + J];
        float zg = gate_sh[2*8 + jj][b] + zr[2*Hh +    J] + bias[2*Hh + J];
        float zo = gate_sh[3*8 + jj][b] + zr[3*Hh +    J] + bias[3*Hh + J];
        float cold = c[b * Hh + J];
        float fg = 1.f / (1.f + expf(-(zf + 1.f)));
        float ig = 1.f / (1.f + expf(-zi));
        float og = 1.f / (1.f + expf(-zo));
        float cn = fg * cold + ig * tanhf(zg);
        float hn = og * tanhf(cn);
        c[b * Hh + J] = cn;
        h_out[b * Hh + J] = hn;
        return;
    }

    {
        int jj = tid >> 5, b = tid & 31;
        int J = jbase + jj;
        #pragma unroll
        for (int g = 0; g < 4; g++)
            g_part[khalf][b][g * Hh + J] = gate_sh[g*8 + jj][b];
    }
    __threadfence();
    if (tid == 0) {
        int old = atomicAdd(&g_cnt[jblk], 1);
        is_finisher = (old == 1);
    }
    __syncthreads();
    if (!is_finisher) return;
    __threadfence();

    {
        int jj = tid >> 5;
        int b  = tid & 31;
        int J  = jbase + jj;
        int ph = 1 - khalf;
        float zi = gate_sh[0*8 + jj][b] + __ldcg(&g_part[ph][b][          J]) + bias[J];
        float zf = gate_sh[1*8 + jj][b] + __ldcg(&g_part[ph][b][  Hh +    J]) + bias[Hh + J];
        float zg = gate_sh[2*8 + jj][b] + __ldcg(&g_part[ph][b][2*Hh +    J]) + bias[2*Hh + J];
        float zo = gate_sh[3*8 + jj][b] + __ldcg(&g_part[ph][b][3*Hh +    J]) + bias[3*Hh + J];
        float cold = c[b * Hh + J];
        float fg = 1.f / (1.f + expf(-(zf + 1.f)));
        float ig = 1.f / (1.f + expf(-zi));
        float og = 1.f / (1.f + expf(-zo));
        float cn = fg * cold + ig * tanhf(zg);
        float hn = og * tanhf(cn);
        c[b * Hh + J] = cn;
        h_out[b * Hh + J] = hn;
    }
    if (tid == 0) g_cnt[jblk] = 0;
}

// ---------------- ZX = gather(Wo, tgt) @ Wx  (TF input hoist, fp32) ----------
__global__ void __launch_bounds__(256, 2) gemm_zx(
    const int* __restrict__ tgt, const float* __restrict__ Wo,
    const float* __restrict__ Wx, float* __restrict__ C)
{
    __shared__ __align__(16) float As[2][8][128];
    __shared__ __align__(16) float Bs[2][8][128];
    int tid = threadIdx.x;
    int nbase = blockIdx.x * 128;
    int mbase = blockIdx.y * 128;
    int tx = tid & 15, ty = tid >> 4;

    ull acc2[8][4];
    #pragma unroll
    for (int i = 0; i < 8; i++)
        #pragma unroll
        for (int jj = 0; jj < 4; jj++) acc2[i][jj] = 0ull;

    int arow = tid >> 1, akq = (tid & 1) * 4;
    int r = mbase + arow;
    int tok = tgt[(r & 31) * Tt + (r >> 5)];
    int bk = tid >> 5, bnq = (tid & 31) * 4;
    const float* Aptr = Wo + (size_t)tok * Dd + akq;
    const float* Bptr = Wx + (size_t)bk * 4096 + nbase + bnq;

    {
        float4 av = *(const float4*)Aptr;
        float4 bv = *(const float4*)Bptr;
        As[0][akq+0][arow] = av.x; As[0][akq+1][arow] = av.y;
        As[0][akq+2][arow] = av.z; As[0][akq+3][arow] = av.w;
        *(float4*)&Bs[0][bk][bnq] = bv;
    }
    __syncthreads();

    int buf = 0;
    for (int k0 = 0; k0 < 1024; k0 += 8) {
        float4 av2, bv2;
        bool has = (k0 + 8) < 1024;
        if (has) {
            av2 = *(const float4*)(Aptr + (k0 + 8));
            bv2 = *(const float4*)(Bptr + (size_t)(k0 + 8) * 4096);
        }
        #pragma unroll
        for (int kk = 0; kk < 8; kk++) {
            float4 a0 = *(const float4*)&As[buf][kk][ty*8];
            float4 a1 = *(const float4*)&As[buf][kk][ty*8 + 4];
            float4 c0 = *(const float4*)&Bs[buf][kk][tx*8];
            float4 c1 = *(const float4*)&Bs[buf][kk][tx*8 + 4];
            ull bw[4];
            bw[0] = pack2(c0.x, c0.y); bw[1] = pack2(c0.z, c0.w);
            bw[2] = pack2(c1.x, c1.y); bw[3] = pack2(c1.z, c1.w);
            float ar[8] = {a0.x,a0.y,a0.z,a0.w,a1.x,a1.y,a1.z,a1.w};
            #pragma unroll
            for (int i = 0; i < 8; i++) {
                ull aw = dup2(ar[i]);
                #pragma unroll
                for (int jj = 0; jj < 4; jj++)
                    acc2[i][jj] = fma2(bw[jj], aw, acc2[i][jj]);
            }
        }
        if (has) {
            int nb = buf ^ 1;
            As[nb][akq+0][arow] = av2.x; As[nb][akq+1][arow] = av2.y;
            As[nb][akq+2][arow] = av2.z; As[nb][akq+3][arow] = av2.w;
            *(float4*)&Bs[nb][bk][bnq] = bv2;
            __syncthreads();
            buf = nb;
        }
    }
    #pragma unroll
    for (int i = 0; i < 8; i++) {
        int row = mbase + ty * 8 + i;
        float* ptr = C + (size_t)row * 4096 + nbase + tx * 8;
        float4 o0 = {lo2(acc2[i][0]), hi2(acc2[i][0]), lo2(acc2[i][1]), hi2(acc2[i][1])};
        float4 o1 = {lo2(acc2[i][2]), hi2(acc2[i][2]), lo2(acc2[i][3]), hi2(acc2[i][3])};
        *(float4*)ptr = o0;
        *(float4*)(ptr + 4) = o1;
    }
}

// ---------------- bf16-split tensor-core logits GEMM ----------------
// C[2048,32000] = A[2048,1024]*B[1024,32000] via AhBh + AhBl + AlBh.
// Inputs are pre-split packed-bf16x2 uints. 128x128 block tile, k-step 16.
// 8 warps: wm in {0,1} (m64), wn in {0..3} (n32). mma.m16n8k16, ldmatrix.
#define A_PITCH 24          // bf16 units (48B, 16B-aligned, ldmatrix conflict-free)
#define B_PITCH 136         // bf16 units (272B)
__global__ void __launch_bounds__(256, 1) gemm_logits_bf16(
    const uint32* __restrict__ Ah, const uint32* __restrict__ Al,
    const uint32* __restrict__ Bh, const uint32* __restrict__ Bl,
    float* __restrict__ C)
{
    __shared__ __align__(16) unsigned short Ash[2][2][128 * A_PITCH];
    __shared__ __align__(16) unsigned short Bsh[2][2][16 * B_PITCH];

    const int tid = threadIdx.x;
    const int lane = tid & 31, warp = tid >> 5;
    const int wm = warp >> 2, wn = warp & 3;
    const int mbase = blockIdx.x * 128;
    const int nbase = blockIdx.y * 128;

    // loader indices: A rows (128) x 8 uints; 2 threads/row x 4 uints
    const int am = tid >> 1, au = tid & 1;
    // B rows (16 k) x 64 uints; 16 threads/row x 4 uints
    const int bkr = tid >> 4, bu = tid & 15;
    const uint32* pAh = Ah + (size_t)(mbase + am) * 512 + au * 4;
    const uint32* pAl = Al + (size_t)(mbase + am) * 512 + au * 4;
    const uint32* pBh = Bh + (size_t)bkr * 16000 + (nbase >> 1) + bu * 4;
    const uint32* pBl = Bl + (size_t)bkr * 16000 + (nbase >> 1) + bu * 4;

    float acc[4][4][4];
    #pragma unroll
    for (int i = 0; i < 4; i++)
        #pragma unroll
        for (int j = 0; j < 4; j++)
            #pragma unroll
            for (int q = 0; q < 4; q++) acc[i][j][q] = 0.f;

    uint4 rah, ral, rbh, rbl;
    rah = *(const uint4*)pAh; ral = *(const uint4*)pAl;
    rbh = *(const uint4*)pBh; rbl = *(const uint4*)pBl;
    *(uint4*)&Ash[0][0][am * A_PITCH + au * 8] = rah;
    *(uint4*)&Ash[0][1][am * A_PITCH + au * 8] = ral;
    *(uint4*)&Bsh[0][0][bkr * B_PITCH + bu * 8] = rbh;
    *(uint4*)&Bsh[0][1][bkr * B_PITCH + bu * 8] = rbl;
    __syncthreads();

    const uint32 aBase = smem_u32(&Ash[0][0][0]);
    const uint32 bBase = smem_u32(&Bsh[0][0][0]);
    const int arow = lane & 15, acol8 = lane >> 4;       // ldmatrix A mapping
    const int brow = ((lane >> 3) & 1) * 8 + (lane & 7); // ldmatrix B mapping
    const int bn8  = (lane >> 4) * 8;
    const uint32 A_HL = 128 * A_PITCH * 2;   // bytes between hi and lo planes
    const uint32 A_BUF = 2 * A_HL;
    const uint32 B_HL = 16 * B_PITCH * 2;
    const uint32 B_BUF = 2 * B_HL;

    int buf = 0;
    for (int kt = 0; kt < 64; kt++) {
        if (kt + 1 < 64) {
            rah = *(const uint4*)(pAh + (kt + 1) * 8);
            ral = *(const uint4*)(pAl + (kt + 1) * 8);
            rbh = *(const uint4*)(pBh + (size_t)(kt + 1) * 16 * 16000);
            rbl = *(const uint4*)(pBl + (size_t)(kt + 1) * 16 * 16000);
        }
        uint32 ah[4][4], al[4][4], bh[2][4], bl[2][4];
        {
            uint32 aOff = aBase + buf * A_BUF;
            #pragma unroll
            for (int mi = 0; mi < 4; mi++) {
                uint32 ad = aOff + (uint32)(((wm * 64 + mi * 16 + arow) * A_PITCH + acol8 * 8) * 2);
                LDSM_X4(ah[mi], ad);
                LDSM_X4(al[mi], ad + A_HL);
            }
            uint32 bOff = bBase + buf * B_BUF;
            #pragma unroll
            for (int c2 = 0; c2 < 2; c2++) {
                uint32 bd = bOff + (uint32)((brow * B_PITCH + wn * 32 + c2 * 16 + bn8) * 2);
                LDSM_X4T(bh[c2], bd);
                LDSM_X4T(bl[c2], bd + B_HL);
            }
        }
        #pragma unroll
        for (int mi = 0; mi < 4; mi++)
            #pragma unroll
            for (int nj = 0; nj < 4; nj++) {
                uint32 h0 = bh[nj >> 1][(nj & 1) * 2], h1 = bh[nj >> 1][(nj & 1) * 2 + 1];
                uint32 l0 = bl[nj >> 1][(nj & 1) * 2], l1 = bl[nj >> 1][(nj & 1) * 2 + 1];
                MMA_BF16(acc[mi][nj], ah[mi], h0, h1);
                MMA_BF16(acc[mi][nj], ah[mi], l0, l1);
                MMA_BF16(acc[mi][nj], al[mi], h0, h1);
            }
        if (kt + 1 < 64) {
            int nb = buf ^ 1;
            *(uint4*)&Ash[nb][0][am * A_PITCH + au * 8] = rah;
            *(uint4*)&Ash[nb][1][am * A_PITCH + au * 8] = ral;
            *(uint4*)&Bsh[nb][0][bkr * B_PITCH + bu * 8] = rbh;
            *(uint4*)&Bsh[nb][1][bkr * B_PITCH + bu * 8] = rbl;
            __syncthreads();
            buf = nb;
        }
    }

    // epilogue: c0,c1 = (row g, cols 2t,2t+1); c2,c3 = (row g+8, same cols)
    #pragma unroll
    for (int mi = 0; mi < 4; mi++)
        #pragma unroll
        for (int nj = 0; nj < 4; nj++) {
            int r0 = mbase + wm * 64 + mi * 16 + (lane >> 2);
            int cb = nbase + wn * 32 + nj * 8 + (lane & 3) * 2;
            *(float2*)&C[(size_t)r0 * Vv + cb] = make_float2(acc[mi][nj][0], acc[mi][nj][1]);
            *(float2*)&C[(size_t)(r0 + 8) * Vv + cb] = make_float2(acc[mi][nj][2], acc[mi][nj][3]);
        }
}

// ---------------- softmax over V per (t,b) row ----------------
__global__ void __launch_bounds__(256) softmax_kernel(
    const float* __restrict__ lg, float* __restrict__ pr)
{
    int row = blockIdx.x;
    const float4* src = (const float4*)(lg + (size_t)row * Vv);
    float4* dst = (float4*)(pr + (size_t)row * Vv);
    const int n4 = Vv / 4;
    int tid = threadIdx.x;

    __shared__ float red[8];
    __shared__ float s_max, s_sum;

    float m = -3.4e38f;
    for (int i = tid; i < n4; i += 256) {
        float4 v = src[i];
        m = fmaxf(m, fmaxf(fmaxf(v.x, v.y), fmaxf(v.z, v.w)));
    }
    #pragma unroll
    for (int o = 16; o; o >>= 1) m = fmaxf(m, __shfl_xor_sync(0xffffffffu, m, o));
    if ((tid & 31) == 0) red[tid >> 5] = m;
    __syncthreads();
    if (tid == 0) {
        float t = red[0];
        #pragma unroll
        for (int i = 1; i < 8; i++) t = fmaxf(t, red[i]);
        s_max = t;
    }
    __syncthreads();
    float rm = s_max;

    float s = 0.f;
    for (int i = tid; i < n4; i += 256) {
        float4 v = src[i];
        s += __expf(v.x - rm) + __expf(v.y - rm) + __expf(v.z - rm) + __expf(v.w - rm);
    }
    #pragma unroll
    for (int o = 16; o; o >>= 1) s += __shfl_xor_sync(0xffffffffu, s, o);
    if ((tid & 31) == 0) red[tid >> 5] = s;
    __syncthreads();
    if (tid == 0) {
        float t = 0.f;
        #pragma unroll
        for (int i = 0; i < 8; i++) t += red[i];
        s_sum = t;
    }
    __syncthreads();
    float inv = 1.f / s_sum;

    for (int i = tid; i < n4; i += 256) {
        float4 v = src[i];
        float4 o;
        o.x = __expf(v.x - rm) * inv; o.y = __expf(v.y - rm) * inv;
        o.z = __expf(v.z - rm) * inv; o.w = __expf(v.w - rm) * inv;
        dst[i] = o;
    }
}

// ---------------- greedy projection (v2, proven): lg = h@Wp + argmax ------
__global__ void __launch_bounds__(256) proj_argmax(
    const float* __restrict__ h, const float* __restrict__ Wp,
    ull* __restrict__ slots)
{
    __shared__ __align__(16) float w_sh[2][16][256];
    __shared__ __align__(16) float x_sh[2][16][36];
    __shared__ ull wred[8][8];

    const int tid = threadIdx.x;
    const int cbase = blockIdx.x * 256;

    const int kr = tid >> 6;
    const int c4 = (tid & 63) * 4;
    const int sb = tid >> 2;
    const int skq = tid & 3;

    const int cg = tid & 63;
    const int b0 = (tid >> 6) * 8;

    ull acc2[4][4];
    #pragma unroll
    for (int i = 0; i < 4; i++)
        #pragma unroll
        for (int jj = 0; jj < 4; jj++) acc2[i][jj] = 0ull;

    float4 wr0, wr1, wr2, wr3, xr;

    {
        const float* wp = Wp + cbase + c4;
        wr0 = *(const float4*)(wp + (size_t)(kr     ) * Vv);
        wr1 = *(const float4*)(wp + (size_t)(kr +  4) * Vv);
        wr2 = *(const float4*)(wp + (size_t)(kr +  8) * Vv);
        wr3 = *(const float4*)(wp + (size_t)(kr + 12) * Vv);
        if (sb < 32) xr = *(const float4*)(h + sb * Hh + skq * 4);
    }
    *(float4*)&w_sh[0][kr     ][c4] = wr0;
    *(float4*)&w_sh[0][kr +  4][c4] = wr1;
    *(float4*)&w_sh[0][kr +  8][c4] = wr2;
    *(float4*)&w_sh[0][kr + 12][c4] = wr3;
    if (sb < 32) {
        x_sh[0][skq*4+0][sb] = xr.x; x_sh[0][skq*4+1][sb] = xr.y;
        x_sh[0][skq*4+2][sb] = xr.z; x_sh[0][skq*4+3][sb] = xr.w;
    }
    __syncthreads();

    int buf = 0;
    for (int ch = 0; ch < 64; ch++) {
        if (ch + 1 < 64) {
            int k0 = (ch + 1) * 16;
            const float* wp = Wp + (size_t)k0 * Vv + cbase + c4;
            wr0 = *(const float4*)(wp + (size_t)(kr     ) * Vv);
            wr1 = *(const float4*)(wp + (size_t)(kr +  4) * Vv);
            wr2 = *(const float4*)(wp + (size_t)(kr +  8) * Vv);
            wr3 = *(const float4*)(wp + (size_t)(kr + 12) * Vv);
            if (sb < 32) xr = *(const float4*)(h + sb * Hh + k0 + skq * 4);
        }
        #pragma unroll
        for (int kk = 0; kk < 16; kk++) {
            float4 w4 = *(const float4*)&w_sh[buf][kk][cg * 4];
            float4 xa = *(const float4*)&x_sh[buf][kk][b0];
            float4 xb4 = *(const float4*)&x_sh[buf][kk][b0 + 4];
            ull x01 = pack2(xa.x, xa.y),  x23 = pack2(xa.z, xa.w);
            ull x45 = pack2(xb4.x, xb4.y), x67 = pack2(xb4.z, xb4.w);
            float wf[4] = {w4.x, w4.y, w4.z, w4.w};
            #pragma unroll
            for (int cc = 0; cc < 4; cc++) {
                ull ww = dup2(wf[cc]);
                acc2[cc][0] = fma2(x01, ww, acc2[cc][0]);
                acc2[cc][1] = fma2(x23, ww, acc2[cc][1]);
                acc2[cc][2] = fma2(x45, ww, acc2[cc][2]);
                acc2[cc][3] = fma2(x67, ww, acc2[cc][3]);
            }
        }
        if (ch + 1 < 64) {
            int nb = buf ^ 1;
            *(float4*)&w_sh[nb][kr     ][c4] = wr0;
            *(float4*)&w_sh[nb][kr +  4][c4] = wr1;
            *(float4*)&w_sh[nb][kr +  8][c4] = wr2;
            *(float4*)&w_sh[nb][kr + 12][c4] = wr3;
            if (sb < 32) {
                x_sh[nb][skq*4+0][sb] = xr.x; x_sh[nb][skq*4+1][sb] = xr.y;
                x_sh[nb][skq*4+2][sb] = xr.z; x_sh[nb][skq*4+3][sb] = xr.w;
            }
            __syncthreads();
            buf = nb;
        }
    }

    ull pk[8];
    #pragma unroll
    for (int i = 0; i < 8; i++) {
        int p = i >> 1;
        ull best = 0ull;
        #pragma unroll
        for (int cc = 0; cc < 4; cc++) {
            float v = (i & 1) ? hi2(acc2[cc][p]) : lo2(acc2[cc][p]);
            unsigned int colg = cbase + cg * 4 + cc;
            ull pkv = ((ull)fkey(v) << 32) | (ull)(0xFFFFFFFFu - colg);
            if (pkv > best) best = pkv;
        }
        pk[i] = best;
    }
    #pragma unroll
    for (int o = 16; o; o >>= 1) {
        #pragma unroll
        for (int i = 0; i < 8; i++) {
            ull other = __shfl_xor_sync(0xffffffffu, pk[i], o);
            if (other > pk[i]) pk[i] = other;
        }
    }
    int w = tid >> 5;
    if ((tid & 31) == 0) {
        #pragma unroll
        for (int i = 0; i < 8; i++) wred[w][i] = pk[i];
    }
    __syncthreads();
    if (tid < 32) {
        int b = tid, bg = b >> 3, bi = b & 7;
        ull m0 = wred[bg * 2][bi];
        ull m1 = wred[bg * 2 + 1][bi];
        if (m1 > m0) m0 = m1;
        atomicMax(&slots[b], m0);
    }
}

__global__ void final_writer(const ull* __restrict__ slots,
                             float* __restrict__ best_out)
{
    int b = threadIdx.x;
    if (b < 32) {
        ull p = slots[b];
        best_out[b] = (float)(0xFFFFFFFFu - (unsigned int)(p & 0xFFFFFFFFull));
    }
}

// ---------------- host orchestration (graph-capturable) ----------------
extern "C" void kernel_launch(void* const* d_in, const int* in_sizes, int n_in,
                              void* d_out, int out_size)
{
    (void)in_sizes; (void)n_in; (void)out_size;
    const int*   tgt  = (const int*)d_in[0];
    const float* Wo   = (const float*)d_in[1];
    const float* Wx   = (const float*)d_in[2];
    const float* Wh   = (const float*)d_in[3];
    const float* bias = (const float*)d_in[4];
    const float* Wp   = (const float*)d_in[5];

    float* out = (float*)d_out;
    float* out_logits = out;
    float* out_probs  = out + (size_t)Tt * Bx * Vv;
    float* out_best   = out + (size_t)2 * Tt * Bx * Vv;

    float *hs, *zxb, *zeros, *ctf, *cgr, *hg0, *hg1;
    ull* slots;
    uint32 *hsh, *hsl, *wph, *wpl;
    cudaGetSymbolAddress((void**)&hs,    g_hs);
    cudaGetSymbolAddress((void**)&zxb,   g_zx);
    cudaGetSymbolAddress((void**)&zeros, g_zeros);
    cudaGetSymbolAddress((void**)&ctf,   g_ctf);
    cudaGetSymbolAddress((void**)&cgr,   g_cgr);
    cudaGetSymbolAddress((void**)&hg0,   g_hg0);
    cudaGetSymbolAddress((void**)&hg1,   g_hg1);
    cudaGetSymbolAddress((void**)&slots, g_slots);
    cudaGetSymbolAddress((void**)&hsh,   g_hsh);
    cudaGetSymbolAddress((void**)&hsl,   g_hsl);
    cudaGetSymbolAddress((void**)&wph,   g_wph);
    cudaGetSymbolAddress((void**)&wpl,   g_wpl);

    init_kernel<<<(BH + 1023) / 1024, 1024>>>();

    // ---- split Wp into bf16 hi/lo (once) ----
    conv_split4<<<(Dd * Vv / 4 + 1023) / 1024, 1024>>>(
        (const float4*)Wp, (uint2*)wph, (uint2*)wpl, Dd * Vv / 4);

    // ---- hoisted TF input projection: ZX = gather(Wo,tgt) @ Wx ----
    gemm_zx<<<dim3(4096 / 128, (Tt * Bx) / 128), 256>>>(tgt, Wo, Wx, zxb);

    // ---- teacher-forced scan ----
    for (int t = 0; t < Tt; t++) {
        lstm_cell<<<128, 256>>>(
            Wx, Wh, bias, Wo,
            nullptr, 0, /*mode=*/3,
            nullptr, nullptr, nullptr,
            (t == 0) ? zeros : hs + (size_t)(t - 1) * BH,
            hs + (size_t)t * BH, ctf,
            zxb + (size_t)t * Bx * 4096);
    }

    // ---- split hs into bf16 hi/lo, then tensor-core logits + softmax ----
    conv_split4<<<((size_t)Tt * BH / 4 + 1023) / 1024, 1024>>>(
        (const float4*)hs, (uint2*)hsh, (uint2*)hsl, Tt * BH / 4);
    gemm_logits_bf16<<<dim3(16, Vv / 128), 256>>>(hsh, hsl, wph, wpl, out_logits);
    softmax_kernel<<<Tt * Bx, 256>>>(out_logits, out_probs);

    // ---- greedy decode ----
    for (int s = 0; s < MX; s++) {
        const float* hi = (s == 0) ? zeros : (((s - 1) & 1) ? hg1 : hg0);
        float* ho = (s & 1) ? hg1 : hg0;
        lstm_cell<<<256, 256>>>(
            Wx, Wh, bias, Wo,
            nullptr, 0, (s == 0) ? 1 : 2,
            (s == 0) ? nullptr : slots + ((s - 1) & 1) * 32,
            slots + (s & 1) * 32,
            (s == 0) ? nullptr : out_best + (size_t)(s - 1) * 32,
            hi, ho, cgr, nullptr);
        proj_argmax<<<Vv / 256, 256>>>(ho, Wp, slots + (s & 1) * 32);
    }
    final_writer<<<1, 32>>>(slots + ((MX - 1) & 1) * 32,
                            out_best + (size_t)(MX - 1) * 32);
}